// round 3
// baseline (speedup 1.0000x reference)
#include <cuda_runtime.h>

#define B_ 8
#define C_ 128
#define H_ 128
#define W_ 224
#define S_ 81
#define HW_ (H_*W_)

// ---------------- scratch (no allocations allowed) ----------------
__device__ float g_corr[B_*S_*HW_];      // 74.3 MB
__device__ float g_h1  [B_*64*HW_];      // 58.7 MB
__device__ float g_h2  [B_*64*HW_];      // 58.7 MB
__device__ float g_h3  [B_*32*HW_];      // 29.3 MB
__device__ float g_w1r [212*9*64];       // weights reordered [ci][k][oc], ci padded to 212
__device__ float g_w2r [64*9*64];
__device__ float g_w3r [64*9*32];

// ---------------- f32x2 packed-FMA helpers (sm_10x) ----------------
__device__ __forceinline__ unsigned long long pk2(float a, float b) {
    unsigned long long r;
    asm("mov.b64 %0, {%1, %2};" : "=l"(r) : "f"(a), "f"(b));
    return r;
}
__device__ __forceinline__ void upk2(unsigned long long r, float& a, float& b) {
    asm("mov.b64 {%0, %1}, %2;" : "=f"(a), "=f"(b) : "l"(r));
}
__device__ __forceinline__ void fma2(unsigned long long& d, unsigned long long a, unsigned long long b) {
    asm("fma.rn.f32x2 %0, %1, %2, %0;" : "+l"(d) : "l"(a), "l"(b));
}

// ---------------- weight reorder: [oc][ci][k] -> [ci][k][oc], zero-pad ci ----------------
__global__ void k_reorder(const float* __restrict__ w, float* __restrict__ wr,
                          int CIN, int CINP, int COUT) {
    int i = blockIdx.x * 256 + threadIdx.x;
    int total = CINP * 9 * COUT;
    if (i >= total) return;
    int oc = i % COUT;
    int t  = i / COUT;
    int k  = t % 9;
    int ci = t / 9;
    wr[i] = (ci < CIN) ? w[(oc * CIN + ci) * 9 + k] : 0.0f;
}

// ---------------- correlation: 81 shifts, mean over 128 channels ----------------
// tile: 32 cols x 8 rows, 1 px/thread, 81 register accumulators. (smem-crossbar bound)
__global__ void __launch_bounds__(256) k_corr(const float* __restrict__ x1,
                                              const float* __restrict__ x2) {
    __shared__ __align__(16) float x2s[4][16][40];
    const int tid = threadIdx.x;
    const int col = tid & 31, row = tid >> 5;
    const int w0 = blockIdx.x * 32, h0 = blockIdx.y * 8, b = blockIdx.z;

    float acc[81];
#pragma unroll
    for (int s = 0; s < 81; s++) acc[s] = 0.f;

    for (int c0 = 0; c0 < C_; c0 += 4) {
        __syncthreads();
        // x2 halo: rows h0-4..h0+11, cols w0-4..w0+35
        for (int idx = tid; idx < 4 * 16 * 40; idx += 256) {
            int c = idx / 640, r2 = idx % 640, rr = r2 / 40, cc = r2 % 40;
            int gh = h0 + rr - 4, gw = w0 + cc - 4;
            float v = 0.f;
            if (gh >= 0 && gh < H_ && gw >= 0 && gw < W_)
                v = x2[((b * C_ + c0 + c) * H_ + gh) * W_ + gw];
            x2s[c][rr][cc] = v;
        }
        float x1r[4];
#pragma unroll
        for (int c = 0; c < 4; c++)
            x1r[c] = x1[((b * C_ + c0 + c) * H_ + h0 + row) * W_ + w0 + col];
        __syncthreads();
#pragma unroll
        for (int c = 0; c < 4; c++) {
            float v = x1r[c];
#pragma unroll
            for (int dy = 0; dy < 9; dy++)
#pragma unroll
                for (int dx = 0; dx < 9; dx++)
                    acc[dy * 9 + dx] += v * x2s[c][row + dy][col + dx];
        }
    }
#pragma unroll
    for (int s = 0; s < 81; s++)
        g_corr[((b * S_ + s) * H_ + h0 + row) * W_ + w0 + col] = acc[s] * (1.0f / 128.0f);
}

// ---------------- direct 3x3 conv, f32x2 accumulators ----------------
// 256 thr = 32 px-threads x 8 oc-threads. Output tile: 8 rows x 32 cols x COUT oc.
// Each thread: 8 rows x OCPT ocs (packed as OCPT/2 f32x2 accumulators).
// Mainloop: kx outer, 10-row input window v[] hoisted across the 3 ky taps
// -> per channel: 30 LDS.32 + 30 pack + 36 LDS.64 + 288 FFMA2 (fma-pipe bound).
// SPLIT: input channels 0..127 from `in` (x1), 128..208 from `in2` (corr).
template<int CIN, int CINP, int COUT, int OCPT, bool LEAKY, bool SPLIT>
__global__ void __launch_bounds__(256) k_conv(const float* __restrict__ in,
                                              const float* __restrict__ in2,
                                              const float* __restrict__ wr,
                                              const float* __restrict__ bias,
                                              float* __restrict__ out) {
    __shared__ __align__(16) float in_s[4][10][34];
    __shared__ __align__(16) float w_s[4 * 9 * COUT];
    const int tid = threadIdx.x;
    const int px = tid & 31, oct = tid >> 5;
    const int w0 = blockIdx.x * 32, h0 = blockIdx.y * 8, b = blockIdx.z;
    const int ocb = oct * OCPT;

    unsigned long long acc[8][OCPT / 2];
#pragma unroll
    for (int j = 0; j < OCPT / 2; j++) {
        unsigned long long bp = pk2(bias[ocb + 2 * j], bias[ocb + 2 * j + 1]);
#pragma unroll
        for (int r = 0; r < 8; r++) acc[r][j] = bp;
    }

    for (int c0 = 0; c0 < CINP; c0 += 4) {
        __syncthreads();
        // input halo for 4 channels: 10 rows x 34 cols each
        for (int idx = tid; idx < 4 * 10 * 34; idx += 256) {
            int c = idx / 340, r2 = idx % 340, rr = r2 / 34, cc = r2 % 34;
            int gh = h0 + rr - 1, gw = w0 + cc - 1;
            int ci = c0 + c;
            float v = 0.f;
            if (gh >= 0 && gh < H_ && gw >= 0 && gw < W_) {
                if (SPLIT) {
                    if (ci < 128)      v = in [((b * 128 + ci)        * H_ + gh) * W_ + gw];
                    else if (ci < 209) v = in2[((b * 81 + (ci - 128)) * H_ + gh) * W_ + gw];
                } else {
                    v = in[((b * CIN + ci) * H_ + gh) * W_ + gw];
                }
            }
            in_s[c][rr][cc] = v;
        }
        // weights chunk [4][9][COUT] is contiguous in wr
        for (int idx = tid; idx < 4 * 9 * COUT; idx += 256)
            w_s[idx] = wr[c0 * 9 * COUT + idx];
        __syncthreads();

#pragma unroll
        for (int c = 0; c < 4; c++) {
#pragma unroll
            for (int kx = 0; kx < 3; kx++) {
                // hoist the 10-row input column window once per (c,kx)
                unsigned long long vv[10];
#pragma unroll
                for (int rr = 0; rr < 10; rr++) {
                    float f = in_s[c][rr][px + kx];
                    vv[rr] = pk2(f, f);
                }
#pragma unroll
                for (int ky = 0; ky < 3; ky++) {
                    const unsigned long long* wrow =
                        reinterpret_cast<const unsigned long long*>(
                            &w_s[((c * 9) + ky * 3 + kx) * COUT + ocb]);
                    unsigned long long wp[OCPT / 2];
#pragma unroll
                    for (int j = 0; j < OCPT / 2; j++) wp[j] = wrow[j];
#pragma unroll
                    for (int r = 0; r < 8; r++) {
#pragma unroll
                        for (int j = 0; j < OCPT / 2; j++) fma2(acc[r][j], vv[r + ky], wp[j]);
                    }
                }
            }
        }
    }

#pragma unroll
    for (int r = 0; r < 8; r++) {
#pragma unroll
        for (int j = 0; j < OCPT / 2; j++) {
            float a, bv;
            upk2(acc[r][j], a, bv);
            if (LEAKY) { a = fmaxf(a, 0.1f * a); bv = fmaxf(bv, 0.1f * bv); }
            int oc = ocb + 2 * j;
            out[((b * COUT + oc    ) * H_ + h0 + r) * W_ + w0 + px] = a;
            out[((b * COUT + oc + 1) * H_ + h0 + r) * W_ + w0 + px] = bv;
        }
    }
}

// ---------------- conv4: 32 -> 2, no activation, tiny ----------------
__global__ void __launch_bounds__(256) k_conv4(const float* __restrict__ in,
                                               const float* __restrict__ w,
                                               const float* __restrict__ bias,
                                               float* __restrict__ out) {
    __shared__ __align__(16) float in_s[4][10][34];
    __shared__ float w_s[2 * 32 * 9];
    const int tid = threadIdx.x;
    const int col = tid & 31, row = tid >> 5;
    const int w0 = blockIdx.x * 32, h0 = blockIdx.y * 8, b = blockIdx.z;

    for (int idx = tid; idx < 576; idx += 256)
        w_s[idx] = w[idx];          // raw [oc][ci][k]
    __syncthreads();

    float acc0 = bias[0], acc1 = bias[1];
    for (int c0 = 0; c0 < 32; c0 += 4) {
        __syncthreads();
        for (int idx = tid; idx < 4 * 10 * 34; idx += 256) {
            int c = idx / 340, r2 = idx % 340, rr = r2 / 34, cc = r2 % 34;
            int gh = h0 + rr - 1, gw = w0 + cc - 1;
            float v = 0.f;
            if (gh >= 0 && gh < H_ && gw >= 0 && gw < W_)
                v = in[((b * 32 + c0 + c) * H_ + gh) * W_ + gw];
            in_s[c][rr][cc] = v;
        }
        __syncthreads();
#pragma unroll
        for (int c = 0; c < 4; c++)
#pragma unroll
            for (int ky = 0; ky < 3; ky++)
#pragma unroll
                for (int kx = 0; kx < 3; kx++) {
                    float v = in_s[c][row + ky][col + kx];
                    int ci = c0 + c, k = ky * 3 + kx;
                    acc0 += v * w_s[      ci * 9 + k];
                    acc1 += v * w_s[288 + ci * 9 + k];
                }
    }
    out[((b * 2 + 0) * H_ + h0 + row) * W_ + w0 + col] = acc0;
    out[((b * 2 + 1) * H_ + h0 + row) * W_ + w0 + col] = acc1;
}

// ---------------- launch ----------------
extern "C" void kernel_launch(void* const* d_in, const int* in_sizes, int n_in,
                              void* d_out, int out_size) {
    (void)in_sizes; (void)n_in; (void)out_size;
    const float* x1 = (const float*)d_in[0];
    const float* x2 = (const float*)d_in[1];
    const float* w1 = (const float*)d_in[2];
    const float* b1 = (const float*)d_in[3];
    const float* w2 = (const float*)d_in[4];
    const float* b2 = (const float*)d_in[5];
    const float* w3 = (const float*)d_in[6];
    const float* b3 = (const float*)d_in[7];
    const float* w4 = (const float*)d_in[8];
    const float* b4 = (const float*)d_in[9];
    float* out = (float*)d_out;

    float *corr, *h1, *h2, *h3, *w1r, *w2r, *w3r;
    cudaGetSymbolAddress((void**)&corr, g_corr);
    cudaGetSymbolAddress((void**)&h1,   g_h1);
    cudaGetSymbolAddress((void**)&h2,   g_h2);
    cudaGetSymbolAddress((void**)&h3,   g_h3);
    cudaGetSymbolAddress((void**)&w1r,  g_w1r);
    cudaGetSymbolAddress((void**)&w2r,  g_w2r);
    cudaGetSymbolAddress((void**)&w3r,  g_w3r);

    k_reorder<<<(212 * 9 * 64 + 255) / 256, 256>>>(w1, w1r, 209, 212, 64);
    k_reorder<<<(64  * 9 * 64 + 255) / 256, 256>>>(w2, w2r, 64, 64, 64);
    k_reorder<<<(64  * 9 * 32 + 255) / 256, 256>>>(w3, w3r, 64, 64, 32);

    dim3 grid(W_ / 32, H_ / 8, B_);   // (7, 16, 8)
    k_corr<<<grid, 256>>>(x1, x2);
    k_conv<209, 212, 64, 8, true,  true ><<<grid, 256>>>(x1, corr, w1r, b1, h1);
    k_conv< 64,  64, 64, 8, true,  false><<<grid, 256>>>(h1, nullptr, w2r, b2, h2);
    k_conv< 64,  64, 32, 4, true,  false><<<grid, 256>>>(h2, nullptr, w3r, b3, h3);
    k_conv4<<<grid, 256>>>(h3, w4, b4, out);
}

// round 4
// speedup vs baseline: 1.2658x; 1.2658x over previous
#include <cuda_runtime.h>
#include <cstdint>

#define B_ 8
#define C_ 128
#define H_ 128
#define W_ 224
#define S_ 81
#define HW_ (H_*W_)

// ---------------- scratch (no allocations allowed) ----------------
__device__ float g_corr[B_*S_*HW_];      // 74.3 MB
__device__ float g_h1  [B_*64*HW_];      // 58.7 MB
__device__ float g_h2  [B_*64*HW_];      // 58.7 MB
__device__ float g_h3  [B_*32*HW_];      // 29.3 MB
__device__ float g_w1r [212*9*64];       // weights reordered [ci][k][oc], ci padded to 212
__device__ float g_w2r [64*9*64];
__device__ float g_w3r [64*9*32];

// ---------------- f32x2 packed-FMA helpers (sm_10x) ----------------
__device__ __forceinline__ unsigned long long pk2(float a, float b) {
    unsigned long long r;
    asm("mov.b64 %0, {%1, %2};" : "=l"(r) : "f"(a), "f"(b));
    return r;
}
__device__ __forceinline__ void upk2(unsigned long long r, float& a, float& b) {
    asm("mov.b64 {%0, %1}, %2;" : "=f"(a), "=f"(b) : "l"(r));
}
__device__ __forceinline__ void fma2(unsigned long long& d, unsigned long long a, unsigned long long b) {
    asm("fma.rn.f32x2 %0, %1, %2, %0;" : "+l"(d) : "l"(a), "l"(b));
}

// ---------------- cp.async helpers ----------------
__device__ __forceinline__ void cpa4(void* smem_dst, const float* gsrc, bool ok) {
    uint32_t d = (uint32_t)__cvta_generic_to_shared(smem_dst);
    asm volatile("cp.async.ca.shared.global [%0], [%1], 4, %2;"
                 :: "r"(d), "l"(gsrc), "r"(ok ? 4 : 0));
}
__device__ __forceinline__ void cpa_commit() {
    asm volatile("cp.async.commit_group;" ::: "memory");
}
__device__ __forceinline__ void cpa_wait_all() {
    asm volatile("cp.async.wait_group 0;" ::: "memory");
}

// ---------------- weight reorder: [oc][ci][k] -> [ci][k][oc], zero-pad ci ----------------
__global__ void k_reorder(const float* __restrict__ w, float* __restrict__ wr,
                          int CIN, int CINP, int COUT) {
    int i = blockIdx.x * 256 + threadIdx.x;
    int total = CINP * 9 * COUT;
    if (i >= total) return;
    int oc = i % COUT;
    int t  = i / COUT;
    int k  = t % 9;
    int ci = t / 9;
    wr[i] = (ci < CIN) ? w[(oc * CIN + ci) * 9 + k] : 0.0f;
}

// ---------------- correlation: 81 shifts, mean over 128 channels ----------------
// tile: 32 cols x 8 rows, 1 px/thread, 81 register accumulators.
// Double-buffered cp.async halo staging; compute is smem-crossbar bound.
__global__ void __launch_bounds__(256, 2) k_corr(const float* __restrict__ x1,
                                                 const float* __restrict__ x2) {
    __shared__ __align__(16) float x2s[2][4][16][40];   // 2 x 10.24 KB
    const int tid = threadIdx.x;
    const int col = tid & 31, row = tid >> 5;
    const int w0 = blockIdx.x * 32, h0 = blockIdx.y * 8, b = blockIdx.z;

    float acc[81];
#pragma unroll
    for (int s = 0; s < 81; s++) acc[s] = 0.f;

    // halo loader: rows h0-4..h0+11, cols w0-4..w0+35 for channels c0..c0+3
    auto load_chunk = [&](int c0, int buf) {
        float* base = &x2s[buf][0][0][0];
        for (int idx = tid; idx < 4 * 16 * 40; idx += 256) {
            int c = idx / 640, r2 = idx % 640, rr = r2 / 40, cc = r2 % 40;
            int gh = h0 + rr - 4, gw = w0 + cc - 4;
            bool ok = (gh >= 0 && gh < H_ && gw >= 0 && gw < W_);
            const float* src = x2 + ((size_t)(b * C_ + c0 + c) * H_ + (ok ? gh : 0)) * W_ + (ok ? gw : 0);
            cpa4(base + idx, src, ok);
        }
    };

    load_chunk(0, 0);
    cpa_commit();

    int p = 0;
    for (int c0 = 0; c0 < C_; c0 += 4, p ^= 1) {
        cpa_wait_all();
        __syncthreads();
        if (c0 + 4 < C_) load_chunk(c0 + 4, p ^ 1);
        cpa_commit();

        float x1r[4];
#pragma unroll
        for (int c = 0; c < 4; c++)
            x1r[c] = x1[((b * C_ + c0 + c) * H_ + h0 + row) * W_ + w0 + col];
#pragma unroll
        for (int c = 0; c < 4; c++) {
            float v = x1r[c];
#pragma unroll
            for (int dy = 0; dy < 9; dy++)
#pragma unroll
                for (int dx = 0; dx < 9; dx++)
                    acc[dy * 9 + dx] += v * x2s[p][c][row + dy][col + dx];
        }
    }
#pragma unroll
    for (int s = 0; s < 81; s++)
        g_corr[((b * S_ + s) * H_ + h0 + row) * W_ + w0 + col] = acc[s] * (1.0f / 128.0f);
}

// ---------------- direct 3x3 conv, f32x2 accumulators, cp.async double buffer ----
// 256 thr = 32 px-threads x 8 oc-threads. Output tile: 8 rows x 32 cols x COUT oc.
// Each thread: 8 rows x OCPT ocs (packed as OCPT/2 f32x2 accumulators).
// SPLIT: input channels 0..127 from `in` (x1), 128..208 from `in2` (corr).
template<int CIN, int CINP, int COUT, int OCPT, bool LEAKY, bool SPLIT>
__global__ void __launch_bounds__(256, 2) k_conv(const float* __restrict__ in,
                                                 const float* __restrict__ in2,
                                                 const float* __restrict__ wr,
                                                 const float* __restrict__ bias,
                                                 float* __restrict__ out) {
    __shared__ __align__(16) float in_s[2][4][10][34];    // 2 x 5.44 KB
    __shared__ __align__(16) float w_s[2][4 * 9 * COUT];  // conv1: 2 x 9.2 KB
    const int tid = threadIdx.x;
    const int px = tid & 31, oct = tid >> 5;
    const int w0 = blockIdx.x * 32, h0 = blockIdx.y * 8, b = blockIdx.z;
    const int ocb = oct * OCPT;

    unsigned long long acc[8][OCPT / 2];
#pragma unroll
    for (int j = 0; j < OCPT / 2; j++) {
        unsigned long long bp = pk2(bias[ocb + 2 * j], bias[ocb + 2 * j + 1]);
#pragma unroll
        for (int r = 0; r < 8; r++) acc[r][j] = bp;
    }

    auto load_chunk = [&](int c0, int buf) {
        float* base = &in_s[buf][0][0][0];
        for (int idx = tid; idx < 4 * 10 * 34; idx += 256) {
            int c = idx / 340, r2 = idx % 340, rr = r2 / 34, cc = r2 % 34;
            int gh = h0 + rr - 1, gw = w0 + cc - 1;
            int ci = c0 + c;
            bool ok = (gh >= 0 && gh < H_ && gw >= 0 && gw < W_);
            int ghc = ok ? gh : 0, gwc = ok ? gw : 0;
            const float* src;
            if (SPLIT) {
                if (ci < 128) {
                    src = in + ((size_t)(b * 128 + ci) * H_ + ghc) * W_ + gwc;
                } else if (ci < 209) {
                    src = in2 + ((size_t)(b * 81 + (ci - 128)) * H_ + ghc) * W_ + gwc;
                } else {
                    src = in; ok = false;
                }
            } else {
                src = in + ((size_t)(b * CIN + ci) * H_ + ghc) * W_ + gwc;
            }
            cpa4(base + idx, src, ok);
        }
        const float* wsrc = wr + (size_t)c0 * 9 * COUT;
        for (int idx = tid; idx < 4 * 9 * COUT; idx += 256)
            cpa4(&w_s[buf][idx], wsrc + idx, true);
    };

    load_chunk(0, 0);
    cpa_commit();

    int p = 0;
    for (int c0 = 0; c0 < CINP; c0 += 4, p ^= 1) {
        cpa_wait_all();
        __syncthreads();
        if (c0 + 4 < CINP) load_chunk(c0 + 4, p ^ 1);
        cpa_commit();

#pragma unroll
        for (int c = 0; c < 4; c++) {
#pragma unroll
            for (int kx = 0; kx < 3; kx++) {
                unsigned long long vv[10];
#pragma unroll
                for (int rr = 0; rr < 10; rr++) {
                    float f = in_s[p][c][rr][px + kx];
                    vv[rr] = pk2(f, f);
                }
#pragma unroll
                for (int ky = 0; ky < 3; ky++) {
                    const unsigned long long* wrow =
                        reinterpret_cast<const unsigned long long*>(
                            &w_s[p][((c * 9) + ky * 3 + kx) * COUT + ocb]);
                    unsigned long long wp[OCPT / 2];
#pragma unroll
                    for (int j = 0; j < OCPT / 2; j++) wp[j] = wrow[j];
#pragma unroll
                    for (int r = 0; r < 8; r++) {
#pragma unroll
                        for (int j = 0; j < OCPT / 2; j++) fma2(acc[r][j], vv[r + ky], wp[j]);
                    }
                }
            }
        }
    }

#pragma unroll
    for (int r = 0; r < 8; r++) {
#pragma unroll
        for (int j = 0; j < OCPT / 2; j++) {
            float a, bv;
            upk2(acc[r][j], a, bv);
            if (LEAKY) { a = fmaxf(a, 0.1f * a); bv = fmaxf(bv, 0.1f * bv); }
            int oc = ocb + 2 * j;
            out[((b * COUT + oc    ) * H_ + h0 + r) * W_ + w0 + px] = a;
            out[((b * COUT + oc + 1) * H_ + h0 + r) * W_ + w0 + px] = bv;
        }
    }
}

// ---------------- conv4: 32 -> 2, no activation, tiny ----------------
__global__ void __launch_bounds__(256, 2) k_conv4(const float* __restrict__ in,
                                                  const float* __restrict__ w,
                                                  const float* __restrict__ bias,
                                                  float* __restrict__ out) {
    __shared__ __align__(16) float in_s[2][4][10][34];
    __shared__ float w_s[2 * 32 * 9];
    const int tid = threadIdx.x;
    const int col = tid & 31, row = tid >> 5;
    const int w0 = blockIdx.x * 32, h0 = blockIdx.y * 8, b = blockIdx.z;

    for (int idx = tid; idx < 576; idx += 256)
        cpa4(&w_s[idx], w + idx, true);          // raw [oc][ci][k]

    auto load_chunk = [&](int c0, int buf) {
        float* base = &in_s[buf][0][0][0];
        for (int idx = tid; idx < 4 * 10 * 34; idx += 256) {
            int c = idx / 340, r2 = idx % 340, rr = r2 / 34, cc = r2 % 34;
            int gh = h0 + rr - 1, gw = w0 + cc - 1;
            bool ok = (gh >= 0 && gh < H_ && gw >= 0 && gw < W_);
            const float* src = in + ((size_t)(b * 32 + c0 + c) * H_ + (ok ? gh : 0)) * W_ + (ok ? gw : 0);
            cpa4(base + idx, src, ok);
        }
    };

    load_chunk(0, 0);
    cpa_commit();

    float acc0 = bias[0], acc1 = bias[1];
    int p = 0;
    for (int c0 = 0; c0 < 32; c0 += 4, p ^= 1) {
        cpa_wait_all();
        __syncthreads();
        if (c0 + 4 < 32) load_chunk(c0 + 4, p ^ 1);
        cpa_commit();
#pragma unroll
        for (int c = 0; c < 4; c++)
#pragma unroll
            for (int ky = 0; ky < 3; ky++)
#pragma unroll
                for (int kx = 0; kx < 3; kx++) {
                    float v = in_s[p][c][row + ky][col + kx];
                    int ci = c0 + c, k = ky * 3 + kx;
                    acc0 += v * w_s[      ci * 9 + k];
                    acc1 += v * w_s[288 + ci * 9 + k];
                }
    }
    out[((b * 2 + 0) * H_ + h0 + row) * W_ + w0 + col] = acc0;
    out[((b * 2 + 1) * H_ + h0 + row) * W_ + w0 + col] = acc1;
}

// ---------------- launch ----------------
extern "C" void kernel_launch(void* const* d_in, const int* in_sizes, int n_in,
                              void* d_out, int out_size) {
    (void)in_sizes; (void)n_in; (void)out_size;
    const float* x1 = (const float*)d_in[0];
    const float* x2 = (const float*)d_in[1];
    const float* w1 = (const float*)d_in[2];
    const float* b1 = (const float*)d_in[3];
    const float* w2 = (const float*)d_in[4];
    const float* b2 = (const float*)d_in[5];
    const float* w3 = (const float*)d_in[6];
    const float* b3 = (const float*)d_in[7];
    const float* w4 = (const float*)d_in[8];
    const float* b4 = (const float*)d_in[9];
    float* out = (float*)d_out;

    float *corr, *h1, *h2, *h3, *w1r, *w2r, *w3r;
    cudaGetSymbolAddress((void**)&corr, g_corr);
    cudaGetSymbolAddress((void**)&h1,   g_h1);
    cudaGetSymbolAddress((void**)&h2,   g_h2);
    cudaGetSymbolAddress((void**)&h3,   g_h3);
    cudaGetSymbolAddress((void**)&w1r,  g_w1r);
    cudaGetSymbolAddress((void**)&w2r,  g_w2r);
    cudaGetSymbolAddress((void**)&w3r,  g_w3r);

    k_reorder<<<(212 * 9 * 64 + 255) / 256, 256>>>(w1, w1r, 209, 212, 64);
    k_reorder<<<(64  * 9 * 64 + 255) / 256, 256>>>(w2, w2r, 64, 64, 64);
    k_reorder<<<(64  * 9 * 32 + 255) / 256, 256>>>(w3, w3r, 64, 64, 32);

    dim3 grid(W_ / 32, H_ / 8, B_);   // (7, 16, 8)
    k_corr<<<grid, 256>>>(x1, x2);
    k_conv<209, 212, 64, 8, true,  true ><<<grid, 256>>>(x1, corr, w1r, b1, h1);
    k_conv< 64,  64, 64, 8, true,  false><<<grid, 256>>>(h1, nullptr, w2r, b2, h2);
    k_conv< 64,  64, 32, 4, true,  false><<<grid, 256>>>(h2, nullptr, w3r, b3, h3);
    k_conv4<<<grid, 256>>>(h3, w4, b4, out);
}

// round 6
// speedup vs baseline: 1.3144x; 1.0384x over previous
#include <cuda_runtime.h>
#include <cuda_bf16.h>
#include <cstdint>

#define B_ 8
#define C_ 128
#define H_ 128
#define W_ 224
#define S_ 81
#define HW_ (H_*W_)

// ---------------- scratch (no allocations allowed) ----------------
__device__ float g_corr[B_*S_*HW_];      // 74.3 MB
__device__ float g_h1  [B_*64*HW_];      // 58.7 MB
__device__ float g_h2  [B_*64*HW_];      // 58.7 MB
__device__ float g_h3  [B_*32*HW_];      // 29.3 MB
// bf16 split weights, layout [oc][K_pad] (K-major rows)
__device__ __nv_bfloat16 g_w1h[64*1920];
__device__ __nv_bfloat16 g_w1l[64*1920];
__device__ __nv_bfloat16 g_w2h[64*576];
__device__ __nv_bfloat16 g_w2l[64*576];
__device__ __nv_bfloat16 g_w3h[32*576];
__device__ __nv_bfloat16 g_w3l[32*576];

// ---------------- helpers ----------------
__device__ __forceinline__ uint32_t smem_u32(const void* p) {
    uint32_t a;
    asm("{ .reg .u64 t; cvta.to.shared.u64 t, %1; cvt.u32.u64 %0, t; }" : "=r"(a) : "l"(p));
    return a;
}
__device__ __forceinline__ void cpa4(void* smem_dst, const float* gsrc, bool ok) {
    uint32_t d = (uint32_t)__cvta_generic_to_shared(smem_dst);
    asm volatile("cp.async.ca.shared.global [%0], [%1], 4, %2;"
                 :: "r"(d), "l"(gsrc), "r"(ok ? 4 : 0));
}
__device__ __forceinline__ void cpa16(uint32_t smem_dst, const void* gsrc) {
    asm volatile("cp.async.cg.shared.global [%0], [%1], 16;"
                 :: "r"(smem_dst), "l"(gsrc));
}
__device__ __forceinline__ void cpa_commit() { asm volatile("cp.async.commit_group;" ::: "memory"); }
__device__ __forceinline__ void cpa_wait_all() { asm volatile("cp.async.wait_group 0;" ::: "memory"); }

__device__ __forceinline__ uint32_t sw128(uint32_t b) { return b ^ ((b >> 3) & 0x70); }

__device__ __forceinline__ void ldsm4(uint32_t* r, uint32_t addr) {
    asm volatile("ldmatrix.sync.aligned.m8n8.x4.shared.b16 {%0,%1,%2,%3}, [%4];"
                 : "=r"(r[0]), "=r"(r[1]), "=r"(r[2]), "=r"(r[3]) : "r"(addr));
}
__device__ __forceinline__ void mma_bf16(float* c, const uint32_t* a, const uint32_t* b) {
    asm volatile("mma.sync.aligned.m16n8k16.row.col.f32.bf16.bf16.f32 "
                 "{%0,%1,%2,%3}, {%4,%5,%6,%7}, {%8,%9}, {%0,%1,%2,%3};"
                 : "+f"(c[0]), "+f"(c[1]), "+f"(c[2]), "+f"(c[3])
                 : "r"(a[0]), "r"(a[1]), "r"(a[2]), "r"(a[3]), "r"(b[0]), "r"(b[1]));
}
__device__ __forceinline__ uint32_t bf16x2(float hi, float lo) {
    uint32_t r;
    asm("cvt.rn.bf16x2.f32 %0, %1, %2;" : "=r"(r) : "f"(hi), "f"(lo));
    return r;
}

// ---------------- weight reorder + bf16 hi/lo split: [oc][ci][3][3] -> [oc][K_pad] ----
__global__ void k_reorder_split(const float* __restrict__ w, __nv_bfloat16* __restrict__ wh,
                                __nv_bfloat16* __restrict__ wl, int CIN, int COUT, int K_pad) {
    int i = blockIdx.x * 256 + threadIdx.x;
    if (i >= COUT * K_pad) return;
    int oc = i / K_pad, kq = i % K_pad;
    float v = 0.0f;
    if (kq < CIN * 9) {
        int c = kq / 9, t9 = kq % 9;
        v = w[(oc * CIN + c) * 9 + t9];
    }
    __nv_bfloat16 h = __float2bfloat16(v);
    wh[i] = h;
    wl[i] = __float2bfloat16(v - __bfloat162float(h));
}

// ---------------- correlation (cp.async double-buffered, unchanged) ----------
__global__ void __launch_bounds__(256, 2) k_corr(const float* __restrict__ x1,
                                                 const float* __restrict__ x2) {
    __shared__ __align__(16) float x2s[2][4][16][40];
    const int tid = threadIdx.x;
    const int col = tid & 31, row = tid >> 5;
    const int w0 = blockIdx.x * 32, h0 = blockIdx.y * 8, b = blockIdx.z;

    float acc[81];
#pragma unroll
    for (int s = 0; s < 81; s++) acc[s] = 0.f;

    auto load_chunk = [&](int c0, int buf) {
        float* base = &x2s[buf][0][0][0];
        for (int idx = tid; idx < 4 * 16 * 40; idx += 256) {
            int c = idx / 640, r2 = idx % 640, rr = r2 / 40, cc = r2 % 40;
            int gh = h0 + rr - 4, gw = w0 + cc - 4;
            bool ok = (gh >= 0 && gh < H_ && gw >= 0 && gw < W_);
            const float* src = x2 + ((size_t)(b * C_ + c0 + c) * H_ + (ok ? gh : 0)) * W_ + (ok ? gw : 0);
            cpa4(base + idx, src, ok);
        }
    };

    load_chunk(0, 0);
    cpa_commit();

    int p = 0;
    for (int c0 = 0; c0 < C_; c0 += 4, p ^= 1) {
        cpa_wait_all();
        __syncthreads();
        if (c0 + 4 < C_) load_chunk(c0 + 4, p ^ 1);
        cpa_commit();

        float x1r[4];
#pragma unroll
        for (int c = 0; c < 4; c++)
            x1r[c] = x1[((b * C_ + c0 + c) * H_ + h0 + row) * W_ + w0 + col];
#pragma unroll
        for (int c = 0; c < 4; c++) {
            float v = x1r[c];
#pragma unroll
            for (int dy = 0; dy < 9; dy++)
#pragma unroll
                for (int dx = 0; dx < 9; dx++)
                    acc[dy * 9 + dx] += v * x2s[p][c][row + dy][col + dx];
        }
    }
#pragma unroll
    for (int s = 0; s < 81; s++)
        g_corr[((b * S_ + s) * H_ + h0 + row) * W_ + w0 + col] = acc[s] * (1.0f / 128.0f);
}

// ---------------- mma.sync implicit-GEMM 3x3 conv (bf16 hi/lo split, f32 acc) -------
// CTA: M=128 px (8 rows x 16 cols), N=COUT. 8 warps: warp w owns px rows 16w..16w+15.
// K chunks of 64 (4 x k16), double buffered. D = Ah*Bh + Ah*Bl + Al*Bh.
template<int CIN, int COUT, int NCHUNK, bool SPLIT>
__global__ void __launch_bounds__(256, 2) k_convmma(const float* __restrict__ in,
                                                    const float* __restrict__ in2,
                                                    const __nv_bfloat16* __restrict__ wh,
                                                    const __nv_bfloat16* __restrict__ wl,
                                                    const float* __restrict__ bias,
                                                    float* __restrict__ out) {
    constexpr int K_pad = NCHUNK * 64;
    constexpr int ASZ = 128 * 128;       // 128 px rows x 128B (64 bf16 k)
    constexpr int BSZ = COUT * 128;      // COUT rows x 128B
    constexpr int NT = COUT / 8;

    extern __shared__ __align__(16) char smem_raw[];
    const uint32_t sb = smem_u32(smem_raw);
    const int tid = threadIdx.x, lane = tid & 31, wrp = tid >> 5;
    const int w0 = blockIdx.x * 16, h0 = blockIdx.y * 8, b = blockIdx.z;

    float acc[NT][4];
#pragma unroll
    for (int nt = 0; nt < NT; nt++)
#pragma unroll
        for (int j = 0; j < 4; j++) acc[nt][j] = 0.f;

    // ldmatrix per-lane address components
    const int sub = lane >> 3, r8 = lane & 7;
    const int am = 16 * wrp + r8 + ((sub & 1) << 3);      // A matrix row (pixel)
    const uint32_t a_row = (uint32_t)am * 128;
    const uint32_t a_xor = (uint32_t)(am & 7) << 4;
    const int ak8 = (sub >> 1) << 3;                      // +8 k for matrices 2,3
    const int bn_l = r8 + ((sub >> 1) << 3);              // B row (oc) within pair
    const int bk8 = (sub & 1) << 3;

    // ---- im2col prefetch: thread owns (pix, k-pair); lanes span pix (coalesced) ----
    float vals[16][2];
    auto load_vals = [&](int i) {
        int k0 = i * 64;
#pragma unroll
        for (int e = 0; e < 16; e++) {
            int idx = tid + e * 256;
            int pix = idx & 127, kk2 = idx >> 7;
#pragma unroll
            for (int j = 0; j < 2; j++) {
                int q = k0 + 2 * kk2 + j;
                int c = q / 9, t9 = q - c * 9, ky = t9 / 3, kx = t9 - ky * 3;
                int gh = h0 + (pix >> 4) + ky - 1, gw = w0 + (pix & 15) + kx - 1;
                bool okb = (gh >= 0 && gh < H_ && gw >= 0 && gw < W_);
                float v = 0.f;
                if (SPLIT) {
                    if (okb && c < 128)      v = in [((size_t)(b * 128 + c) * H_ + gh) * W_ + gw];
                    else if (okb && c < 209) v = in2[((size_t)(b * 81 + (c - 128)) * H_ + gh) * W_ + gw];
                } else {
                    if (okb && c < CIN)      v = in [((size_t)(b * CIN + c) * H_ + gh) * W_ + gw];
                }
                vals[e][j] = v;
            }
        }
    };
    auto stage_A = [&](int buf) {
        char* ah = smem_raw + (size_t)(buf * 2 + 0) * ASZ;
        char* al = smem_raw + (size_t)(buf * 2 + 1) * ASZ;
#pragma unroll
        for (int e = 0; e < 16; e++) {
            int idx = tid + e * 256;
            int pix = idx & 127, kk2 = idx >> 7;
            float v0 = vals[e][0], v1 = vals[e][1];
            uint32_t hp = bf16x2(v1, v0);                      // hi halves = rn(v1), lo = rn(v0)
            float h0f = __uint_as_float(hp << 16);
            float h1f = __uint_as_float(hp & 0xffff0000u);
            uint32_t lp = bf16x2(v1 - h1f, v0 - h0f);
            uint32_t off = (uint32_t)pix * 128 + (((uint32_t)kk2 * 4) ^ ((uint32_t)(pix & 7) << 4));
            *(uint32_t*)(ah + off) = hp;
            *(uint32_t*)(al + off) = lp;
        }
    };
    auto stage_B = [&](int i, int buf) {
        int k0 = i * 64;
#pragma unroll
        for (int j = 0; j < COUT * 16 / 256; j++) {
            int q = tid + j * 256;
            int split = q / (COUT * 8);
            int r = q - split * (COUT * 8);
            int oc = r >> 3, seg = r & 7;
            const __nv_bfloat16* src = (split ? wl : wh) + (size_t)oc * K_pad + k0 + seg * 8;
            uint32_t byte = (uint32_t)(oc * 128 + seg * 16);
            cpa16(sb + 4 * ASZ + (uint32_t)(buf * 2 + split) * BSZ + sw128(byte), src);
        }
        cpa_commit();
    };

    load_vals(0);
    stage_A(0);
    stage_B(0, 0);

    for (int i = 0; i < NCHUNK; i++) {
        const int p = i & 1;
        cpa_wait_all();
        __syncthreads();
        if (i + 1 < NCHUNK) { stage_B(i + 1, p ^ 1); load_vals(i + 1); }

        const uint32_t Ah = sb + (uint32_t)(p * 2 + 0) * ASZ;
        const uint32_t Al = sb + (uint32_t)(p * 2 + 1) * ASZ;
        const uint32_t Bh = sb + 4 * ASZ + (uint32_t)(p * 2 + 0) * BSZ;
        const uint32_t Bl = sb + 4 * ASZ + (uint32_t)(p * 2 + 1) * BSZ;
#pragma unroll
        for (int kc = 0; kc < 4; kc++) {
            uint32_t ka = ((uint32_t)((kc * 16 + ak8) * 2)) ^ a_xor;
            uint32_t ah[4], al[4];
            ldsm4(ah, Ah + a_row + ka);
            ldsm4(al, Al + a_row + ka);
#pragma unroll
            for (int tp = 0; tp < NT / 2; tp++) {
                int bn = tp * 16 + bn_l;
                uint32_t boff = (uint32_t)bn * 128
                              + (((uint32_t)((kc * 16 + bk8) * 2)) ^ ((uint32_t)(bn & 7) << 4));
                uint32_t bh[4], bl[4];
                ldsm4(bh, Bh + boff);
                ldsm4(bl, Bl + boff);
                mma_bf16(acc[2 * tp],     ah, bh);
                mma_bf16(acc[2 * tp],     ah, bl);
                mma_bf16(acc[2 * tp],     al, bh);
                mma_bf16(acc[2 * tp + 1], ah, bh + 2);
                mma_bf16(acc[2 * tp + 1], ah, bl + 2);
                mma_bf16(acc[2 * tp + 1], al, bh + 2);
            }
        }
        if (i + 1 < NCHUNK) stage_A(p ^ 1);
    }

    // ---- epilogue: registers -> gmem NCHW, bias + leaky ----
    const int m1 = 16 * wrp + lane / 4, m2 = m1 + 8;
    const int cb = (lane % 4) * 2;
    const int gh1 = h0 + (m1 >> 4), gw1 = w0 + (m1 & 15);
    const int gh2 = h0 + (m2 >> 4), gw2 = w0 + (m2 & 15);
#pragma unroll
    for (int nt = 0; nt < NT; nt++) {
        int n0 = nt * 8 + cb;
        float b0v = bias[n0], b1v = bias[n0 + 1];
        float v00 = acc[nt][0] + b0v, v01 = acc[nt][1] + b1v;
        float v10 = acc[nt][2] + b0v, v11 = acc[nt][3] + b1v;
        v00 = fmaxf(v00, 0.1f * v00); v01 = fmaxf(v01, 0.1f * v01);
        v10 = fmaxf(v10, 0.1f * v10); v11 = fmaxf(v11, 0.1f * v11);
        out[((size_t)(b * COUT + n0    ) * H_ + gh1) * W_ + gw1] = v00;
        out[((size_t)(b * COUT + n0 + 1) * H_ + gh1) * W_ + gw1] = v01;
        out[((size_t)(b * COUT + n0    ) * H_ + gh2) * W_ + gw2] = v10;
        out[((size_t)(b * COUT + n0 + 1) * H_ + gh2) * W_ + gw2] = v11;
    }
}

// ---------------- conv4: 32 -> 2, no activation (unchanged) ----------------
__global__ void __launch_bounds__(256, 2) k_conv4(const float* __restrict__ in,
                                                  const float* __restrict__ w,
                                                  const float* __restrict__ bias,
                                                  float* __restrict__ out) {
    __shared__ __align__(16) float in_s[2][4][10][34];
    __shared__ float w_s[2 * 32 * 9];
    const int tid = threadIdx.x;
    const int col = tid & 31, row = tid >> 5;
    const int w0 = blockIdx.x * 32, h0 = blockIdx.y * 8, b = blockIdx.z;

    for (int idx = tid; idx < 576; idx += 256)
        cpa4(&w_s[idx], w + idx, true);

    auto load_chunk = [&](int c0, int buf) {
        float* base = &in_s[buf][0][0][0];
        for (int idx = tid; idx < 4 * 10 * 34; idx += 256) {
            int c = idx / 340, r2 = idx % 340, rr = r2 / 34, cc = r2 % 34;
            int gh = h0 + rr - 1, gw = w0 + cc - 1;
            bool ok = (gh >= 0 && gh < H_ && gw >= 0 && gw < W_);
            const float* src = in + ((size_t)(b * 32 + c0 + c) * H_ + (ok ? gh : 0)) * W_ + (ok ? gw : 0);
            cpa4(base + idx, src, ok);
        }
    };

    load_chunk(0, 0);
    cpa_commit();

    float acc0 = bias[0], acc1 = bias[1];
    int p = 0;
    for (int c0 = 0; c0 < 32; c0 += 4, p ^= 1) {
        cpa_wait_all();
        __syncthreads();
        if (c0 + 4 < 32) load_chunk(c0 + 4, p ^ 1);
        cpa_commit();
#pragma unroll
        for (int c = 0; c < 4; c++)
#pragma unroll
            for (int ky = 0; ky < 3; ky++)
#pragma unroll
                for (int kx = 0; kx < 3; kx++) {
                    float v = in_s[p][c][row + ky][col + kx];
                    int ci = c0 + c, k = ky * 3 + kx;
                    acc0 += v * w_s[      ci * 9 + k];
                    acc1 += v * w_s[288 + ci * 9 + k];
                }
    }
    out[((b * 2 + 0) * H_ + h0 + row) * W_ + w0 + col] = acc0;
    out[((b * 2 + 1) * H_ + h0 + row) * W_ + w0 + col] = acc1;
}

// ---------------- launch ----------------
extern "C" void kernel_launch(void* const* d_in, const int* in_sizes, int n_in,
                              void* d_out, int out_size) {
    (void)in_sizes; (void)n_in; (void)out_size;
    const float* x1 = (const float*)d_in[0];
    const float* x2 = (const float*)d_in[1];
    const float* w1 = (const float*)d_in[2];
    const float* b1 = (const float*)d_in[3];
    const float* w2 = (const float*)d_in[4];
    const float* b2 = (const float*)d_in[5];
    const float* w3 = (const float*)d_in[6];
    const float* b3 = (const float*)d_in[7];
    const float* w4 = (const float*)d_in[8];
    const float* b4 = (const float*)d_in[9];
    float* out = (float*)d_out;

    float *corr, *h1, *h2, *h3;
    __nv_bfloat16 *w1h, *w1l, *w2h, *w2l, *w3h, *w3l;
    cudaGetSymbolAddress((void**)&corr, g_corr);
    cudaGetSymbolAddress((void**)&h1,   g_h1);
    cudaGetSymbolAddress((void**)&h2,   g_h2);
    cudaGetSymbolAddress((void**)&h3,   g_h3);
    cudaGetSymbolAddress((void**)&w1h,  g_w1h);
    cudaGetSymbolAddress((void**)&w1l,  g_w1l);
    cudaGetSymbolAddress((void**)&w2h,  g_w2h);
    cudaGetSymbolAddress((void**)&w2l,  g_w2l);
    cudaGetSymbolAddress((void**)&w3h,  g_w3h);
    cudaGetSymbolAddress((void**)&w3l,  g_w3l);

    // smem: 4 A tiles (16KB each) + 4 B tiles
    constexpr int SM64 = 4 * 16384 + 4 * 64 * 128;   // 98304
    constexpr int SM32 = 4 * 16384 + 4 * 32 * 128;   // 81920
    static bool attr_done = false;
    if (!attr_done) {
        cudaFuncSetAttribute(k_convmma<209, 64, 30, true >, cudaFuncAttributeMaxDynamicSharedMemorySize, SM64);
        cudaFuncSetAttribute(k_convmma< 64, 64,  9, false>, cudaFuncAttributeMaxDynamicSharedMemorySize, SM64);
        cudaFuncSetAttribute(k_convmma< 64, 32,  9, false>, cudaFuncAttributeMaxDynamicSharedMemorySize, SM32);
        attr_done = true;
    }

    k_reorder_split<<<(64 * 1920 + 255) / 256, 256>>>(w1, w1h, w1l, 209, 64, 1920);
    k_reorder_split<<<(64 * 576  + 255) / 256, 256>>>(w2, w2h, w2l,  64, 64,  576);
    k_reorder_split<<<(32 * 576  + 255) / 256, 256>>>(w3, w3h, w3l,  64, 32,  576);

    dim3 gridC(W_ / 32, H_ / 8, B_);   // (7, 16, 8)  corr / conv4
    dim3 gridT(W_ / 16, H_ / 8, B_);   // (14, 16, 8) mma convs

    k_corr<<<gridC, 256>>>(x1, x2);
    k_convmma<209, 64, 30, true ><<<gridT, 256, SM64>>>(x1, corr, w1h, w1l, b1, h1);
    k_convmma< 64, 64,  9, false><<<gridT, 256, SM64>>>(h1, nullptr, w2h, w2l, b2, h2);
    k_convmma< 64, 32,  9, false><<<gridT, 256, SM32>>>(h2, nullptr, w3h, w3l, b3, h3);
    k_conv4<<<gridC, 256>>>(h3, w4, b4, out);
}

// round 7
// speedup vs baseline: 1.9615x; 1.4923x over previous
#include <cuda_runtime.h>
#include <cuda_bf16.h>
#include <cstdint>

#define B_ 8
#define C_ 128
#define H_ 128
#define W_ 224
#define S_ 81
#define HW_ (H_*W_)

// ---------------- scratch (no allocations allowed) ----------------
__device__ float g_corr[B_*S_*HW_];      // 74.3 MB
__device__ float g_h1  [B_*64*HW_];      // 58.7 MB
__device__ float g_h2  [B_*64*HW_];      // 58.7 MB
__device__ float g_h3  [B_*32*HW_];      // 29.3 MB
// bf16 split weights, layout [shift s][oc][Cpad] (channel-major rows)
__device__ __nv_bfloat16 g_w1h[9*64*256];
__device__ __nv_bfloat16 g_w1l[9*64*256];
__device__ __nv_bfloat16 g_w2h[9*64*64];
__device__ __nv_bfloat16 g_w2l[9*64*64];
__device__ __nv_bfloat16 g_w3h[9*32*64];
__device__ __nv_bfloat16 g_w3l[9*32*64];

// ---------------- helpers ----------------
__device__ __forceinline__ uint32_t smem_u32(const void* p) {
    uint32_t a;
    asm("{ .reg .u64 t; cvta.to.shared.u64 t, %1; cvt.u32.u64 %0, t; }" : "=r"(a) : "l"(p));
    return a;
}
__device__ __forceinline__ void cpa4(void* smem_dst, const float* gsrc, bool ok) {
    uint32_t d = (uint32_t)__cvta_generic_to_shared(smem_dst);
    asm volatile("cp.async.ca.shared.global [%0], [%1], 4, %2;"
                 :: "r"(d), "l"(gsrc), "r"(ok ? 4 : 0));
}
__device__ __forceinline__ void cpa16(uint32_t smem_dst, const void* gsrc) {
    asm volatile("cp.async.cg.shared.global [%0], [%1], 16;"
                 :: "r"(smem_dst), "l"(gsrc));
}
__device__ __forceinline__ void cpa_commit() { asm volatile("cp.async.commit_group;" ::: "memory"); }
__device__ __forceinline__ void cpa_wait_all() { asm volatile("cp.async.wait_group 0;" ::: "memory"); }

__device__ __forceinline__ uint32_t sw128(uint32_t b) { return b ^ ((b >> 3) & 0x70); }

__device__ __forceinline__ void ldsm4(uint32_t* r, uint32_t addr) {
    asm volatile("ldmatrix.sync.aligned.m8n8.x4.shared.b16 {%0,%1,%2,%3}, [%4];"
                 : "=r"(r[0]), "=r"(r[1]), "=r"(r[2]), "=r"(r[3]) : "r"(addr));
}
__device__ __forceinline__ void mma_bf16(float* c, const uint32_t* a, const uint32_t* b) {
    asm volatile("mma.sync.aligned.m16n8k16.row.col.f32.bf16.bf16.f32 "
                 "{%0,%1,%2,%3}, {%4,%5,%6,%7}, {%8,%9}, {%0,%1,%2,%3};"
                 : "+f"(c[0]), "+f"(c[1]), "+f"(c[2]), "+f"(c[3])
                 : "r"(a[0]), "r"(a[1]), "r"(a[2]), "r"(a[3]), "r"(b[0]), "r"(b[1]));
}
__device__ __forceinline__ uint32_t bf16x2(float hi, float lo) {
    uint32_t r;
    asm("cvt.rn.bf16x2.f32 %0, %1, %2;" : "=r"(r) : "f"(hi), "f"(lo));
    return r;
}

// ------- weight reorder + split: [oc][ci][3][3] -> [s][oc][Cpad], zero-pad c -------
__global__ void k_reorder_split(const float* __restrict__ w, __nv_bfloat16* __restrict__ wh,
                                __nv_bfloat16* __restrict__ wl, int CIN, int COUT, int Cpad) {
    int i = blockIdx.x * 256 + threadIdx.x;
    if (i >= 9 * COUT * Cpad) return;
    int c = i % Cpad;
    int t2 = i / Cpad;
    int oc = t2 % COUT, s = t2 / COUT;
    float v = (c < CIN) ? w[(oc * CIN + c) * 9 + s] : 0.0f;
    __nv_bfloat16 h = __float2bfloat16(v);
    wh[i] = h;
    wl[i] = __float2bfloat16(v - __bfloat162float(h));
}

// ---------------- correlation (cp.async double-buffered, unchanged) ----------
__global__ void __launch_bounds__(256, 2) k_corr(const float* __restrict__ x1,
                                                 const float* __restrict__ x2) {
    __shared__ __align__(16) float x2s[2][4][16][40];
    const int tid = threadIdx.x;
    const int col = tid & 31, row = tid >> 5;
    const int w0 = blockIdx.x * 32, h0 = blockIdx.y * 8, b = blockIdx.z;

    float acc[81];
#pragma unroll
    for (int s = 0; s < 81; s++) acc[s] = 0.f;

    auto load_chunk = [&](int c0, int buf) {
        float* base = &x2s[buf][0][0][0];
        for (int idx = tid; idx < 4 * 16 * 40; idx += 256) {
            int c = idx / 640, r2 = idx % 640, rr = r2 / 40, cc = r2 % 40;
            int gh = h0 + rr - 4, gw = w0 + cc - 4;
            bool ok = (gh >= 0 && gh < H_ && gw >= 0 && gw < W_);
            const float* src = x2 + ((size_t)(b * C_ + c0 + c) * H_ + (ok ? gh : 0)) * W_ + (ok ? gw : 0);
            cpa4(base + idx, src, ok);
        }
    };

    load_chunk(0, 0);
    cpa_commit();

    int p = 0;
    for (int c0 = 0; c0 < C_; c0 += 4, p ^= 1) {
        cpa_wait_all();
        __syncthreads();
        if (c0 + 4 < C_) load_chunk(c0 + 4, p ^ 1);
        cpa_commit();

        float x1r[4];
#pragma unroll
        for (int c = 0; c < 4; c++)
            x1r[c] = x1[((b * C_ + c0 + c) * H_ + h0 + row) * W_ + w0 + col];
#pragma unroll
        for (int c = 0; c < 4; c++) {
            float v = x1r[c];
#pragma unroll
            for (int dy = 0; dy < 9; dy++)
#pragma unroll
                for (int dx = 0; dx < 9; dx++)
                    acc[dy * 9 + dx] += v * x2s[p][c][row + dy][col + dx];
        }
    }
#pragma unroll
    for (int s = 0; s < 81; s++)
        g_corr[((b * S_ + s) * H_ + h0 + row) * W_ + w0 + col] = acc[s] * (1.0f / 128.0f);
}

// ------- shift-decomposed mma.sync conv: 3x3 = 9 shifted 1x1 GEMMs, K = channels ----
// CTA: M=128 px (8 rows x 16 cols), N=COUT. Halo tile 10x18 px x 64ch (hi/lo bf16,
// SW128) staged once per channel chunk; ldmatrix reads A directly from the halo
// with per-shift row offsets. B [s][oc][c] double-buffered per shift via cp.async.
// D = Ah*Bh + Ah*Bl + Al*Bh (f32 acc).
template<int CIN, int Cpad, int NCHUNK, int COUT, bool SPLIT>
__global__ void __launch_bounds__(256, 2) k_convmma(const float* __restrict__ in,
                                                    const float* __restrict__ in2,
                                                    const __nv_bfloat16* __restrict__ wh,
                                                    const __nv_bfloat16* __restrict__ wl,
                                                    const float* __restrict__ bias,
                                                    float* __restrict__ out) {
    constexpr int ASZ = 180 * 128;       // halo: 180 px rows x 128B (64ch bf16)
    constexpr int BSZ = COUT * 128;      // B tile: COUT rows x 128B
    constexpr int NT = COUT / 8;

    extern __shared__ __align__(16) char smem_raw[];
    const uint32_t sb = smem_u32(smem_raw);
    const uint32_t Ah = sb, Al = sb + ASZ, Bb = sb + 2 * ASZ;
    const int tid = threadIdx.x, lane = tid & 31, wrp = tid >> 5;
    const int w0 = blockIdx.x * 16, h0 = blockIdx.y * 8, b = blockIdx.z;

    float acc[NT][4];
#pragma unroll
    for (int nt = 0; nt < NT; nt++)
#pragma unroll
        for (int j = 0; j < 4; j++) acc[nt][j] = 0.f;

    // ldmatrix per-lane components (same frag convention as validated R6 kernel)
    const int sub = lane >> 3, r8 = lane & 7;
    const int am = 16 * wrp + r8 + ((sub & 1) << 3);      // A matrix row (pixel in tile)
    const int pr = am >> 4, pc = am & 15;
    const int ak8 = (sub >> 1) << 3;
    const int bn_l = r8 + ((sub >> 1) << 3);
    const int bk8 = (sub & 1) << 3;

    // ---- halo stage: (c2, hpix) per element; 2 channels packed per 4B store ----
    auto stage_halo = [&](int i) {
        for (int e = tid; e < 32 * 180; e += 256) {
            int c2 = e / 180, hp = e - c2 * 180;
            int hr = hp / 18, hc = hp - hr * 18;
            int gh = h0 + hr - 1, gw = w0 + hc - 1;
            bool okp = (gh >= 0 && gh < H_ && gw >= 0 && gw < W_);
            int c0 = i * 64 + c2 * 2;
            float v0 = 0.f, v1 = 0.f;
            if (okp) {
                if (SPLIT) {
                    if (c0 < 128) {
                        v0 = in[((size_t)(b * 128 + c0    ) * H_ + gh) * W_ + gw];
                        v1 = in[((size_t)(b * 128 + c0 + 1) * H_ + gh) * W_ + gw];
                    } else {
                        if (c0     < 209) v0 = in2[((size_t)(b * 81 + (c0     - 128)) * H_ + gh) * W_ + gw];
                        if (c0 + 1 < 209) v1 = in2[((size_t)(b * 81 + (c0 + 1 - 128)) * H_ + gh) * W_ + gw];
                    }
                } else {
                    v0 = in[((size_t)(b * CIN + c0    ) * H_ + gh) * W_ + gw];
                    v1 = in[((size_t)(b * CIN + c0 + 1) * H_ + gh) * W_ + gw];
                }
            }
            uint32_t hpk = bf16x2(v1, v0);
            float l0 = v0 - __uint_as_float(hpk << 16);
            float l1 = v1 - __uint_as_float(hpk & 0xffff0000u);
            uint32_t lpk = bf16x2(l1, l0);
            uint32_t off = (uint32_t)hp * 128 + (((uint32_t)c2 * 4) ^ ((uint32_t)(hp & 7) << 4));
            *(uint32_t*)(smem_raw + off)       = hpk;
            *(uint32_t*)(smem_raw + ASZ + off) = lpk;
        }
    };
    // ---- B prefetch for global shift-iteration t1 into buffer `buf` ----
    auto stage_B = [&](int t1, int buf) {
        int s = t1 % 9, i = t1 / 9;
#pragma unroll
        for (int j = 0; j < COUT * 16 / 256; j++) {
            int q = tid + j * 256;
            int split = q / (COUT * 8);
            int r = q - split * (COUT * 8);
            int oc = r >> 3, seg = r & 7;
            const __nv_bfloat16* src =
                (split ? wl : wh) + (size_t)(s * COUT + oc) * Cpad + i * 64 + seg * 8;
            cpa16(Bb + (uint32_t)(buf * 2 + split) * BSZ + sw128((uint32_t)(oc * 128 + seg * 16)), src);
        }
        cpa_commit();
    };

    stage_B(0, 0);
    int t = 0, buf = 0;
    for (int i = 0; i < NCHUNK; i++) {
        __syncthreads();                 // all warps done reading previous halo
        stage_halo(i);
#pragma unroll 1
        for (int s = 0; s < 9; s++) {
            cpa_wait_all();              // current B landed
            __syncthreads();             // halo + B visible; warps aligned
            if (t + 1 < NCHUNK * 9) stage_B(t + 1, buf ^ 1);

            const int ky = s / 3, kx = s - ky * 3;
            const int hr = (pr + ky) * 18 + (pc + kx);
            const uint32_t arow = (uint32_t)hr * 128;
            const uint32_t axor = (uint32_t)(hr & 7) << 4;
            const uint32_t Bhc = Bb + (uint32_t)(buf * 2 + 0) * BSZ;
            const uint32_t Blc = Bb + (uint32_t)(buf * 2 + 1) * BSZ;
#pragma unroll
            for (int kc = 0; kc < 4; kc++) {
                uint32_t ka = ((uint32_t)((kc * 16 + ak8) * 2)) ^ axor;
                uint32_t ahf[4], alf[4];
                ldsm4(ahf, Ah + arow + ka);
                ldsm4(alf, Al + arow + ka);
#pragma unroll
                for (int tp = 0; tp < NT / 2; tp++) {
                    int bn = tp * 16 + bn_l;
                    uint32_t boff = (uint32_t)bn * 128
                                  + (((uint32_t)((kc * 16 + bk8) * 2)) ^ ((uint32_t)(bn & 7) << 4));
                    uint32_t bhf[4], blf[4];
                    ldsm4(bhf, Bhc + boff);
                    ldsm4(blf, Blc + boff);
                    mma_bf16(acc[2 * tp],     ahf, bhf);
                    mma_bf16(acc[2 * tp],     ahf, blf);
                    mma_bf16(acc[2 * tp],     alf, bhf);
                    mma_bf16(acc[2 * tp + 1], ahf, bhf + 2);
                    mma_bf16(acc[2 * tp + 1], ahf, blf + 2);
                    mma_bf16(acc[2 * tp + 1], alf, bhf + 2);
                }
            }
            buf ^= 1; t++;
        }
    }

    // ---- epilogue: registers -> gmem NCHW, bias + leaky ----
    const int m1 = 16 * wrp + lane / 4, m2 = m1 + 8;
    const int cb = (lane % 4) * 2;
    const int gh1 = h0 + (m1 >> 4), gw1 = w0 + (m1 & 15);
    const int gh2 = h0 + (m2 >> 4), gw2 = w0 + (m2 & 15);
#pragma unroll
    for (int nt = 0; nt < NT; nt++) {
        int n0 = nt * 8 + cb;
        float b0v = bias[n0], b1v = bias[n0 + 1];
        float v00 = acc[nt][0] + b0v, v01 = acc[nt][1] + b1v;
        float v10 = acc[nt][2] + b0v, v11 = acc[nt][3] + b1v;
        v00 = fmaxf(v00, 0.1f * v00); v01 = fmaxf(v01, 0.1f * v01);
        v10 = fmaxf(v10, 0.1f * v10); v11 = fmaxf(v11, 0.1f * v11);
        out[((size_t)(b * COUT + n0    ) * H_ + gh1) * W_ + gw1] = v00;
        out[((size_t)(b * COUT + n0 + 1) * H_ + gh1) * W_ + gw1] = v01;
        out[((size_t)(b * COUT + n0    ) * H_ + gh2) * W_ + gw2] = v10;
        out[((size_t)(b * COUT + n0 + 1) * H_ + gh2) * W_ + gw2] = v11;
    }
}

// ---------------- conv4: 32 -> 2, no activation (unchanged) ----------------
__global__ void __launch_bounds__(256, 2) k_conv4(const float* __restrict__ in,
                                                  const float* __restrict__ w,
                                                  const float* __restrict__ bias,
                                                  float* __restrict__ out) {
    __shared__ __align__(16) float in_s[2][4][10][34];
    __shared__ float w_s[2 * 32 * 9];
    const int tid = threadIdx.x;
    const int col = tid & 31, row = tid >> 5;
    const int w0 = blockIdx.x * 32, h0 = blockIdx.y * 8, b = blockIdx.z;

    for (int idx = tid; idx < 576; idx += 256)
        cpa4(&w_s[idx], w + idx, true);

    auto load_chunk = [&](int c0, int buf) {
        float* base = &in_s[buf][0][0][0];
        for (int idx = tid; idx < 4 * 10 * 34; idx += 256) {
            int c = idx / 340, r2 = idx % 340, rr = r2 / 34, cc = r2 % 34;
            int gh = h0 + rr - 1, gw = w0 + cc - 1;
            bool ok = (gh >= 0 && gh < H_ && gw >= 0 && gw < W_);
            const float* src = in + ((size_t)(b * 32 + c0 + c) * H_ + (ok ? gh : 0)) * W_ + (ok ? gw : 0);
            cpa4(base + idx, src, ok);
        }
    };

    load_chunk(0, 0);
    cpa_commit();

    float acc0 = bias[0], acc1 = bias[1];
    int p = 0;
    for (int c0 = 0; c0 < 32; c0 += 4, p ^= 1) {
        cpa_wait_all();
        __syncthreads();
        if (c0 + 4 < 32) load_chunk(c0 + 4, p ^ 1);
        cpa_commit();
#pragma unroll
        for (int c = 0; c < 4; c++)
#pragma unroll
            for (int ky = 0; ky < 3; ky++)
#pragma unroll
                for (int kx = 0; kx < 3; kx++) {
                    float v = in_s[p][c][row + ky][col + kx];
                    int ci = c0 + c, k = ky * 3 + kx;
                    acc0 += v * w_s[      ci * 9 + k];
                    acc1 += v * w_s[288 + ci * 9 + k];
                }
    }
    out[((b * 2 + 0) * H_ + h0 + row) * W_ + w0 + col] = acc0;
    out[((b * 2 + 1) * H_ + h0 + row) * W_ + w0 + col] = acc1;
}

// ---------------- launch ----------------
extern "C" void kernel_launch(void* const* d_in, const int* in_sizes, int n_in,
                              void* d_out, int out_size) {
    (void)in_sizes; (void)n_in; (void)out_size;
    const float* x1 = (const float*)d_in[0];
    const float* x2 = (const float*)d_in[1];
    const float* w1 = (const float*)d_in[2];
    const float* b1 = (const float*)d_in[3];
    const float* w2 = (const float*)d_in[4];
    const float* b2 = (const float*)d_in[5];
    const float* w3 = (const float*)d_in[6];
    const float* b3 = (const float*)d_in[7];
    const float* w4 = (const float*)d_in[8];
    const float* b4 = (const float*)d_in[9];
    float* out = (float*)d_out;

    float *corr, *h1, *h2, *h3;
    __nv_bfloat16 *w1h, *w1l, *w2h, *w2l, *w3h, *w3l;
    cudaGetSymbolAddress((void**)&corr, g_corr);
    cudaGetSymbolAddress((void**)&h1,   g_h1);
    cudaGetSymbolAddress((void**)&h2,   g_h2);
    cudaGetSymbolAddress((void**)&h3,   g_h3);
    cudaGetSymbolAddress((void**)&w1h,  g_w1h);
    cudaGetSymbolAddress((void**)&w1l,  g_w1l);
    cudaGetSymbolAddress((void**)&w2h,  g_w2h);
    cudaGetSymbolAddress((void**)&w2l,  g_w2l);
    cudaGetSymbolAddress((void**)&w3h,  g_w3h);
    cudaGetSymbolAddress((void**)&w3l,  g_w3l);

    // smem: hi/lo halo (2 x 23040) + B double buffer (2 x 2 x BSZ)
    constexpr int SM64 = 2 * 180 * 128 + 4 * 64 * 128;   // 78848
    constexpr int SM32 = 2 * 180 * 128 + 4 * 32 * 128;   // 62464
    static bool attr_done = false;
    if (!attr_done) {
        cudaFuncSetAttribute(k_convmma<209, 256, 4, 64, true >, cudaFuncAttributeMaxDynamicSharedMemorySize, SM64);
        cudaFuncSetAttribute(k_convmma< 64,  64, 1, 64, false>, cudaFuncAttributeMaxDynamicSharedMemorySize, SM64);
        cudaFuncSetAttribute(k_convmma< 64,  64, 1, 32, false>, cudaFuncAttributeMaxDynamicSharedMemorySize, SM32);
        attr_done = true;
    }

    k_reorder_split<<<(9 * 64 * 256 + 255) / 256, 256>>>(w1, w1h, w1l, 209, 64, 256);
    k_reorder_split<<<(9 * 64 * 64  + 255) / 256, 256>>>(w2, w2h, w2l,  64, 64,  64);
    k_reorder_split<<<(9 * 32 * 64  + 255) / 256, 256>>>(w3, w3h, w3l,  64, 32,  64);

    dim3 gridC(W_ / 32, H_ / 8, B_);   // (7, 16, 8)  corr / conv4
    dim3 gridT(W_ / 16, H_ / 8, B_);   // (14, 16, 8) mma convs

    k_corr<<<gridC, 256>>>(x1, x2);
    k_convmma<209, 256, 4, 64, true ><<<gridT, 256, SM64>>>(x1, corr, w1h, w1l, b1, h1);
    k_convmma< 64,  64, 1, 64, false><<<gridT, 256, SM64>>>(h1, nullptr, w2h, w2l, b2, h2);
    k_convmma< 64,  64, 1, 32, false><<<gridT, 256, SM32>>>(h2, nullptr, w3h, w3l, b3, h3);
    k_conv4<<<gridC, 256>>>(h3, w4, b4, out);
}

// round 8
// speedup vs baseline: 1.9896x; 1.0143x over previous
#include <cuda_runtime.h>
#include <cuda_bf16.h>
#include <cstdint>

#define B_ 8
#define C_ 128
#define H_ 128
#define W_ 224
#define S_ 81
#define HW_ (H_*W_)

// ---------------- scratch (no allocations allowed) ----------------
__device__ float g_corr[B_*S_*HW_];      // 74.3 MB
__device__ float g_h1  [B_*64*HW_];      // 58.7 MB
__device__ float g_h2  [B_*64*HW_];      // 58.7 MB
__device__ float g_h3  [B_*32*HW_];      // 29.3 MB
// bf16 split weights, layout [shift s][oc][Cpad] (channel-major rows)
__device__ __nv_bfloat16 g_w1h[9*64*256];
__device__ __nv_bfloat16 g_w1l[9*64*256];
__device__ __nv_bfloat16 g_w2h[9*64*64];
__device__ __nv_bfloat16 g_w2l[9*64*64];
__device__ __nv_bfloat16 g_w3h[9*32*64];
__device__ __nv_bfloat16 g_w3l[9*32*64];

// ---------------- helpers ----------------
__device__ __forceinline__ uint32_t smem_u32(const void* p) {
    uint32_t a;
    asm("{ .reg .u64 t; cvta.to.shared.u64 t, %1; cvt.u32.u64 %0, t; }" : "=r"(a) : "l"(p));
    return a;
}
__device__ __forceinline__ void cpa4(void* smem_dst, const float* gsrc, bool ok) {
    uint32_t d = (uint32_t)__cvta_generic_to_shared(smem_dst);
    asm volatile("cp.async.ca.shared.global [%0], [%1], 4, %2;"
                 :: "r"(d), "l"(gsrc), "r"(ok ? 4 : 0));
}
__device__ __forceinline__ void cpa16(uint32_t smem_dst, const void* gsrc) {
    asm volatile("cp.async.cg.shared.global [%0], [%1], 16;"
                 :: "r"(smem_dst), "l"(gsrc));
}
__device__ __forceinline__ void cpa_commit() { asm volatile("cp.async.commit_group;" ::: "memory"); }
__device__ __forceinline__ void cpa_wait_all() { asm volatile("cp.async.wait_group 0;" ::: "memory"); }

__device__ __forceinline__ uint32_t sw128(uint32_t b) { return b ^ ((b >> 3) & 0x70); }

__device__ __forceinline__ void ldsm4(uint32_t* r, uint32_t addr) {
    asm volatile("ldmatrix.sync.aligned.m8n8.x4.shared.b16 {%0,%1,%2,%3}, [%4];"
                 : "=r"(r[0]), "=r"(r[1]), "=r"(r[2]), "=r"(r[3]) : "r"(addr));
}
__device__ __forceinline__ void mma_bf16(float* c, const uint32_t* a, const uint32_t* b) {
    asm volatile("mma.sync.aligned.m16n8k16.row.col.f32.bf16.bf16.f32 "
                 "{%0,%1,%2,%3}, {%4,%5,%6,%7}, {%8,%9}, {%0,%1,%2,%3};"
                 : "+f"(c[0]), "+f"(c[1]), "+f"(c[2]), "+f"(c[3])
                 : "r"(a[0]), "r"(a[1]), "r"(a[2]), "r"(a[3]), "r"(b[0]), "r"(b[1]));
}
__device__ __forceinline__ uint32_t bf16x2(float hi, float lo) {
    uint32_t r;
    asm("cvt.rn.bf16x2.f32 %0, %1, %2;" : "=r"(r) : "f"(hi), "f"(lo));
    return r;
}

// ------- weight reorder + split: [oc][ci][3][3] -> [s][oc][Cpad], zero-pad c -------
__global__ void k_reorder_split(const float* __restrict__ w, __nv_bfloat16* __restrict__ wh,
                                __nv_bfloat16* __restrict__ wl, int CIN, int COUT, int Cpad) {
    int i = blockIdx.x * 256 + threadIdx.x;
    if (i >= 9 * COUT * Cpad) return;
    int c = i % Cpad;
    int t2 = i / Cpad;
    int oc = t2 % COUT, s = t2 / COUT;
    float v = (c < CIN) ? w[(oc * CIN + c) * 9 + s] : 0.0f;
    __nv_bfloat16 h = __float2bfloat16(v);
    wh[i] = h;
    wl[i] = __float2bfloat16(v - __bfloat162float(h));
}

// ---------------- correlation (cp.async double-buffered, unchanged) ----------
__global__ void __launch_bounds__(256, 2) k_corr(const float* __restrict__ x1,
                                                 const float* __restrict__ x2) {
    __shared__ __align__(16) float x2s[2][4][16][40];
    const int tid = threadIdx.x;
    const int col = tid & 31, row = tid >> 5;
    const int w0 = blockIdx.x * 32, h0 = blockIdx.y * 8, b = blockIdx.z;

    float acc[81];
#pragma unroll
    for (int s = 0; s < 81; s++) acc[s] = 0.f;

    auto load_chunk = [&](int c0, int buf) {
        float* base = &x2s[buf][0][0][0];
        for (int idx = tid; idx < 4 * 16 * 40; idx += 256) {
            int c = idx / 640, r2 = idx % 640, rr = r2 / 40, cc = r2 % 40;
            int gh = h0 + rr - 4, gw = w0 + cc - 4;
            bool ok = (gh >= 0 && gh < H_ && gw >= 0 && gw < W_);
            const float* src = x2 + ((size_t)(b * C_ + c0 + c) * H_ + (ok ? gh : 0)) * W_ + (ok ? gw : 0);
            cpa4(base + idx, src, ok);
        }
    };

    load_chunk(0, 0);
    cpa_commit();

    int p = 0;
    for (int c0 = 0; c0 < C_; c0 += 4, p ^= 1) {
        cpa_wait_all();
        __syncthreads();
        if (c0 + 4 < C_) load_chunk(c0 + 4, p ^ 1);
        cpa_commit();

        float x1r[4];
#pragma unroll
        for (int c = 0; c < 4; c++)
            x1r[c] = x1[((b * C_ + c0 + c) * H_ + h0 + row) * W_ + w0 + col];
#pragma unroll
        for (int c = 0; c < 4; c++) {
            float v = x1r[c];
#pragma unroll
            for (int dy = 0; dy < 9; dy++)
#pragma unroll
                for (int dx = 0; dx < 9; dx++)
                    acc[dy * 9 + dx] += v * x2s[p][c][row + dy][col + dx];
        }
    }
#pragma unroll
    for (int s = 0; s < 81; s++)
        g_corr[((b * S_ + s) * H_ + h0 + row) * W_ + w0 + col] = acc[s] * (1.0f / 128.0f);
}

// ------- shift-decomposed mma.sync conv: 3x3 = 9 shifted 1x1 GEMMs, K = channels ----
// CTA: M=128 px (8 rows x 16 cols), N=COUT. Halo tile 10x18 px x 64ch (hi/lo bf16,
// SW128) staged once per channel chunk; ldmatrix reads A directly from the halo.
// B [s][oc][c] double-buffered per shift via cp.async.
// D = Ah*Bh + Ah*Bl + Al*Bh (f32 acc), issued pass-major so each accumulator is
// reused only every 2*NT mma (no dependent-chain stalls).
template<int CIN, int Cpad, int NCHUNK, int COUT, bool SPLIT>
__global__ void __launch_bounds__(256, 2) k_convmma(const float* __restrict__ in,
                                                    const float* __restrict__ in2,
                                                    const __nv_bfloat16* __restrict__ wh,
                                                    const __nv_bfloat16* __restrict__ wl,
                                                    const float* __restrict__ bias,
                                                    float* __restrict__ out) {
    constexpr int ASZ = 180 * 128;       // halo: 180 px rows x 128B (64ch bf16)
    constexpr int BSZ = COUT * 128;      // B tile: COUT rows x 128B
    constexpr int NT = COUT / 8;
    constexpr int NTP = NT / 2;

    extern __shared__ __align__(16) char smem_raw[];
    const uint32_t sb = smem_u32(smem_raw);
    const uint32_t Ah = sb, Al = sb + ASZ, Bb = sb + 2 * ASZ;
    const int tid = threadIdx.x, lane = tid & 31, wrp = tid >> 5;
    const int w0 = blockIdx.x * 16, h0 = blockIdx.y * 8, b = blockIdx.z;

    float acc[NT][4];
#pragma unroll
    for (int nt = 0; nt < NT; nt++)
#pragma unroll
        for (int j = 0; j < 4; j++) acc[nt][j] = 0.f;

    // ldmatrix per-lane components
    const int sub = lane >> 3, r8 = lane & 7;
    const int am = 16 * wrp + r8 + ((sub & 1) << 3);      // A matrix row (pixel in tile)
    const int pr = am >> 4, pc = am & 15;
    const int ak8 = (sub >> 1) << 3;
    const int bn_l = r8 + ((sub >> 1) << 3);
    const int bk8 = (sub & 1) << 3;

    // ---- halo stage: (c2, hpix) per element; 2 channels packed per 4B store ----
    auto stage_halo = [&](int i) {
        for (int e = tid; e < 32 * 180; e += 256) {
            int c2 = e / 180, hp = e - c2 * 180;
            int hr = hp / 18, hc = hp - hr * 18;
            int gh = h0 + hr - 1, gw = w0 + hc - 1;
            bool okp = (gh >= 0 && gh < H_ && gw >= 0 && gw < W_);
            int c0 = i * 64 + c2 * 2;
            float v0 = 0.f, v1 = 0.f;
            if (okp) {
                if (SPLIT) {
                    if (c0 < 128) {
                        v0 = in[((size_t)(b * 128 + c0    ) * H_ + gh) * W_ + gw];
                        v1 = in[((size_t)(b * 128 + c0 + 1) * H_ + gh) * W_ + gw];
                    } else {
                        if (c0     < 209) v0 = in2[((size_t)(b * 81 + (c0     - 128)) * H_ + gh) * W_ + gw];
                        if (c0 + 1 < 209) v1 = in2[((size_t)(b * 81 + (c0 + 1 - 128)) * H_ + gh) * W_ + gw];
                    }
                } else {
                    v0 = in[((size_t)(b * CIN + c0    ) * H_ + gh) * W_ + gw];
                    v1 = in[((size_t)(b * CIN + c0 + 1) * H_ + gh) * W_ + gw];
                }
            }
            uint32_t hpk = bf16x2(v1, v0);
            float l0 = v0 - __uint_as_float(hpk << 16);
            float l1 = v1 - __uint_as_float(hpk & 0xffff0000u);
            uint32_t lpk = bf16x2(l1, l0);
            uint32_t off = (uint32_t)hp * 128 + (((uint32_t)c2 * 4) ^ ((uint32_t)(hp & 7) << 4));
            *(uint32_t*)(smem_raw + off)       = hpk;
            *(uint32_t*)(smem_raw + ASZ + off) = lpk;
        }
    };
    // ---- B prefetch for global shift-iteration t1 into buffer `buf` ----
    auto stage_B = [&](int t1, int buf) {
        int s = t1 % 9, i = t1 / 9;
#pragma unroll
        for (int j = 0; j < COUT * 16 / 256; j++) {
            int q = tid + j * 256;
            int split = q / (COUT * 8);
            int r = q - split * (COUT * 8);
            int oc = r >> 3, seg = r & 7;
            const __nv_bfloat16* src =
                (split ? wl : wh) + (size_t)(s * COUT + oc) * Cpad + i * 64 + seg * 8;
            cpa16(Bb + (uint32_t)(buf * 2 + split) * BSZ + sw128((uint32_t)(oc * 128 + seg * 16)), src);
        }
        cpa_commit();
    };

    stage_B(0, 0);
    int t = 0, buf = 0;
    for (int i = 0; i < NCHUNK; i++) {
        __syncthreads();                 // all warps done reading previous halo
        stage_halo(i);
        // last conv1 chunk holds only channels 192..208 -> 2 k16 steps suffice
        const int kcmax = (SPLIT && i == NCHUNK - 1) ? 2 : 4;
#pragma unroll 1
        for (int s = 0; s < 9; s++) {
            cpa_wait_all();              // current B landed
            __syncthreads();             // halo + B visible; warps aligned
            if (t + 1 < NCHUNK * 9) stage_B(t + 1, buf ^ 1);

            const int ky = s / 3, kx = s - ky * 3;
            const int hr = (pr + ky) * 18 + (pc + kx);
            const uint32_t arow = (uint32_t)hr * 128;
            const uint32_t axor = (uint32_t)(hr & 7) << 4;
            const uint32_t Bhc = Bb + (uint32_t)(buf * 2 + 0) * BSZ;
            const uint32_t Blc = Bb + (uint32_t)(buf * 2 + 1) * BSZ;
#pragma unroll
            for (int kc = 0; kc < 4; kc++) {
                if (kc < kcmax) {
                    uint32_t ka = ((uint32_t)((kc * 16 + ak8) * 2)) ^ axor;
                    uint32_t ahf[4], alf[4];
                    ldsm4(ahf, Ah + arow + ka);
                    ldsm4(alf, Al + arow + ka);
                    uint32_t bhf[NTP][4], blf[NTP][4];
#pragma unroll
                    for (int tp = 0; tp < NTP; tp++) {
                        int bn = tp * 16 + bn_l;
                        uint32_t boff = (uint32_t)bn * 128
                                      + (((uint32_t)((kc * 16 + bk8) * 2)) ^ ((uint32_t)(bn & 7) << 4));
                        ldsm4(bhf[tp], Bhc + boff);
                        ldsm4(blf[tp], Blc + boff);
                    }
                    // pass-major, accumulator-minor: same acc reused every 2*NT mma
#pragma unroll
                    for (int tp = 0; tp < NTP; tp++) {
                        mma_bf16(acc[2 * tp],     ahf, bhf[tp]);
                        mma_bf16(acc[2 * tp + 1], ahf, bhf[tp] + 2);
                    }
#pragma unroll
                    for (int tp = 0; tp < NTP; tp++) {
                        mma_bf16(acc[2 * tp],     ahf, blf[tp]);
                        mma_bf16(acc[2 * tp + 1], ahf, blf[tp] + 2);
                    }
#pragma unroll
                    for (int tp = 0; tp < NTP; tp++) {
                        mma_bf16(acc[2 * tp],     alf, bhf[tp]);
                        mma_bf16(acc[2 * tp + 1], alf, bhf[tp] + 2);
                    }
                }
            }
            buf ^= 1; t++;
        }
    }

    // ---- epilogue: registers -> gmem NCHW, bias + leaky ----
    const int m1 = 16 * wrp + lane / 4, m2 = m1 + 8;
    const int cb = (lane % 4) * 2;
    const int gh1 = h0 + (m1 >> 4), gw1 = w0 + (m1 & 15);
    const int gh2 = h0 + (m2 >> 4), gw2 = w0 + (m2 & 15);
#pragma unroll
    for (int nt = 0; nt < NT; nt++) {
        int n0 = nt * 8 + cb;
        float b0v = bias[n0], b1v = bias[n0 + 1];
        float v00 = acc[nt][0] + b0v, v01 = acc[nt][1] + b1v;
        float v10 = acc[nt][2] + b0v, v11 = acc[nt][3] + b1v;
        v00 = fmaxf(v00, 0.1f * v00); v01 = fmaxf(v01, 0.1f * v01);
        v10 = fmaxf(v10, 0.1f * v10); v11 = fmaxf(v11, 0.1f * v11);
        out[((size_t)(b * COUT + n0    ) * H_ + gh1) * W_ + gw1] = v00;
        out[((size_t)(b * COUT + n0 + 1) * H_ + gh1) * W_ + gw1] = v01;
        out[((size_t)(b * COUT + n0    ) * H_ + gh2) * W_ + gw2] = v10;
        out[((size_t)(b * COUT + n0 + 1) * H_ + gh2) * W_ + gw2] = v11;
    }
}

// ---------------- conv4: 32 -> 2, no activation (unchanged) ----------------
__global__ void __launch_bounds__(256, 2) k_conv4(const float* __restrict__ in,
                                                  const float* __restrict__ w,
                                                  const float* __restrict__ bias,
                                                  float* __restrict__ out) {
    __shared__ __align__(16) float in_s[2][4][10][34];
    __shared__ float w_s[2 * 32 * 9];
    const int tid = threadIdx.x;
    const int col = tid & 31, row = tid >> 5;
    const int w0 = blockIdx.x * 32, h0 = blockIdx.y * 8, b = blockIdx.z;

    for (int idx = tid; idx < 576; idx += 256)
        cpa4(&w_s[idx], w + idx, true);

    auto load_chunk = [&](int c0, int buf) {
        float* base = &in_s[buf][0][0][0];
        for (int idx = tid; idx < 4 * 10 * 34; idx += 256) {
            int c = idx / 340, r2 = idx % 340, rr = r2 / 34, cc = r2 % 34;
            int gh = h0 + rr - 1, gw = w0 + cc - 1;
            bool ok = (gh >= 0 && gh < H_ && gw >= 0 && gw < W_);
            const float* src = in + ((size_t)(b * 32 + c0 + c) * H_ + (ok ? gh : 0)) * W_ + (ok ? gw : 0);
            cpa4(base + idx, src, ok);
        }
    };

    load_chunk(0, 0);
    cpa_commit();

    float acc0 = bias[0], acc1 = bias[1];
    int p = 0;
    for (int c0 = 0; c0 < 32; c0 += 4, p ^= 1) {
        cpa_wait_all();
        __syncthreads();
        if (c0 + 4 < 32) load_chunk(c0 + 4, p ^ 1);
        cpa_commit();
#pragma unroll
        for (int c = 0; c < 4; c++)
#pragma unroll
            for (int ky = 0; ky < 3; ky++)
#pragma unroll
                for (int kx = 0; kx < 3; kx++) {
                    float v = in_s[p][c][row + ky][col + kx];
                    int ci = c0 + c, k = ky * 3 + kx;
                    acc0 += v * w_s[      ci * 9 + k];
                    acc1 += v * w_s[288 + ci * 9 + k];
                }
    }
    out[((b * 2 + 0) * H_ + h0 + row) * W_ + w0 + col] = acc0;
    out[((b * 2 + 1) * H_ + h0 + row) * W_ + w0 + col] = acc1;
}

// ---------------- launch ----------------
extern "C" void kernel_launch(void* const* d_in, const int* in_sizes, int n_in,
                              void* d_out, int out_size) {
    (void)in_sizes; (void)n_in; (void)out_size;
    const float* x1 = (const float*)d_in[0];
    const float* x2 = (const float*)d_in[1];
    const float* w1 = (const float*)d_in[2];
    const float* b1 = (const float*)d_in[3];
    const float* w2 = (const float*)d_in[4];
    const float* b2 = (const float*)d_in[5];
    const float* w3 = (const float*)d_in[6];
    const float* b3 = (const float*)d_in[7];
    const float* w4 = (const float*)d_in[8];
    const float* b4 = (const float*)d_in[9];
    float* out = (float*)d_out;

    float *corr, *h1, *h2, *h3;
    __nv_bfloat16 *w1h, *w1l, *w2h, *w2l, *w3h, *w3l;
    cudaGetSymbolAddress((void**)&corr, g_corr);
    cudaGetSymbolAddress((void**)&h1,   g_h1);
    cudaGetSymbolAddress((void**)&h2,   g_h2);
    cudaGetSymbolAddress((void**)&h3,   g_h3);
    cudaGetSymbolAddress((void**)&w1h,  g_w1h);
    cudaGetSymbolAddress((void**)&w1l,  g_w1l);
    cudaGetSymbolAddress((void**)&w2h,  g_w2h);
    cudaGetSymbolAddress((void**)&w2l,  g_w2l);
    cudaGetSymbolAddress((void**)&w3h,  g_w3h);
    cudaGetSymbolAddress((void**)&w3l,  g_w3l);

    // smem: hi/lo halo (2 x 23040) + B double buffer (2 x 2 x BSZ)
    constexpr int SM64 = 2 * 180 * 128 + 4 * 64 * 128;   // 78848
    constexpr int SM32 = 2 * 180 * 128 + 4 * 32 * 128;   // 62464
    static bool attr_done = false;
    if (!attr_done) {
        cudaFuncSetAttribute(k_convmma<209, 256, 4, 64, true >, cudaFuncAttributeMaxDynamicSharedMemorySize, SM64);
        cudaFuncSetAttribute(k_convmma< 64,  64, 1, 64, false>, cudaFuncAttributeMaxDynamicSharedMemorySize, SM64);
        cudaFuncSetAttribute(k_convmma< 64,  64, 1, 32, false>, cudaFuncAttributeMaxDynamicSharedMemorySize, SM32);
        attr_done = true;
    }

    k_reorder_split<<<(9 * 64 * 256 + 255) / 256, 256>>>(w1, w1h, w1l, 209, 64, 256);
    k_reorder_split<<<(9 * 64 * 64  + 255) / 256, 256>>>(w2, w2h, w2l,  64, 64,  64);
    k_reorder_split<<<(9 * 32 * 64  + 255) / 256, 256>>>(w3, w3h, w3l,  64, 32,  64);

    dim3 gridC(W_ / 32, H_ / 8, B_);   // (7, 16, 8)  corr / conv4
    dim3 gridT(W_ / 16, H_ / 8, B_);   // (14, 16, 8) mma convs

    k_corr<<<gridC, 256>>>(x1, x2);
    k_convmma<209, 256, 4, 64, true ><<<gridT, 256, SM64>>>(x1, corr, w1h, w1l, b1, h1);
    k_convmma< 64,  64, 1, 64, false><<<gridT, 256, SM64>>>(h1, nullptr, w2h, w2l, b2, h2);
    k_convmma< 64,  64, 1, 32, false><<<gridT, 256, SM32>>>(h2, nullptr, w3h, w3l, b3, h3);
    k_conv4<<<gridC, 256>>>(h3, w4, b4, out);
}

// round 9
// speedup vs baseline: 2.0319x; 1.0213x over previous
#include <cuda_runtime.h>
#include <cuda_bf16.h>
#include <cstdint>

#define B_ 8
#define C_ 128
#define H_ 128
#define W_ 224
#define S_ 81
#define HW_ (H_*W_)

// ---------------- scratch (no allocations allowed) ----------------
__device__ float g_corr[B_*S_*HW_];      // 74.3 MB
__device__ float g_h1  [B_*64*HW_];      // 58.7 MB
__device__ float g_h2  [B_*64*HW_];      // 58.7 MB
__device__ float g_h3  [B_*32*HW_];      // 29.3 MB
// bf16 split weights, layout [shift s][oc][Cpad] (channel-major rows)
__device__ __nv_bfloat16 g_w1h[9*64*256];
__device__ __nv_bfloat16 g_w1l[9*64*256];
__device__ __nv_bfloat16 g_w2h[9*64*64];
__device__ __nv_bfloat16 g_w2l[9*64*64];
__device__ __nv_bfloat16 g_w3h[9*32*64];
__device__ __nv_bfloat16 g_w3l[9*32*64];
__device__ __nv_bfloat16 g_w4h[9*16*64];   // oc padded 2->16
__device__ __nv_bfloat16 g_w4l[9*16*64];

// ---------------- helpers ----------------
__device__ __forceinline__ uint32_t smem_u32(const void* p) {
    uint32_t a;
    asm("{ .reg .u64 t; cvta.to.shared.u64 t, %1; cvt.u32.u64 %0, t; }" : "=r"(a) : "l"(p));
    return a;
}
__device__ __forceinline__ void cpa4(void* smem_dst, const float* gsrc, bool ok) {
    uint32_t d = (uint32_t)__cvta_generic_to_shared(smem_dst);
    asm volatile("cp.async.ca.shared.global [%0], [%1], 4, %2;"
                 :: "r"(d), "l"(gsrc), "r"(ok ? 4 : 0));
}
__device__ __forceinline__ void cpa16(uint32_t smem_dst, const void* gsrc) {
    asm volatile("cp.async.cg.shared.global [%0], [%1], 16;"
                 :: "r"(smem_dst), "l"(gsrc));
}
__device__ __forceinline__ void cpa_commit() { asm volatile("cp.async.commit_group;" ::: "memory"); }
__device__ __forceinline__ void cpa_wait_all() { asm volatile("cp.async.wait_group 0;" ::: "memory"); }
__device__ __forceinline__ void cpa_wait1()   { asm volatile("cp.async.wait_group 1;" ::: "memory"); }

__device__ __forceinline__ uint32_t sw128(uint32_t b) { return b ^ ((b >> 3) & 0x70); }

__device__ __forceinline__ void ldsm4(uint32_t* r, uint32_t addr) {
    asm volatile("ldmatrix.sync.aligned.m8n8.x4.shared.b16 {%0,%1,%2,%3}, [%4];"
                 : "=r"(r[0]), "=r"(r[1]), "=r"(r[2]), "=r"(r[3]) : "r"(addr));
}
__device__ __forceinline__ void mma_bf16(float* c, const uint32_t* a, const uint32_t* b) {
    asm volatile("mma.sync.aligned.m16n8k16.row.col.f32.bf16.bf16.f32 "
                 "{%0,%1,%2,%3}, {%4,%5,%6,%7}, {%8,%9}, {%0,%1,%2,%3};"
                 : "+f"(c[0]), "+f"(c[1]), "+f"(c[2]), "+f"(c[3])
                 : "r"(a[0]), "r"(a[1]), "r"(a[2]), "r"(a[3]), "r"(b[0]), "r"(b[1]));
}
__device__ __forceinline__ uint32_t bf16x2(float hi, float lo) {
    uint32_t r;
    asm("cvt.rn.bf16x2.f32 %0, %1, %2;" : "=r"(r) : "f"(hi), "f"(lo));
    return r;
}

// ------- weight reorder + split: [oc][ci][3][3] -> [s][oc][Cpad], zero-pad c & oc ----
__global__ void k_reorder_split(const float* __restrict__ w, __nv_bfloat16* __restrict__ wh,
                                __nv_bfloat16* __restrict__ wl, int CIN, int COUT, int Cpad,
                                int COUTR) {
    int i = blockIdx.x * 256 + threadIdx.x;
    if (i >= 9 * COUT * Cpad) return;
    int c = i % Cpad;
    int t2 = i / Cpad;
    int oc = t2 % COUT, s = t2 / COUT;
    float v = (c < CIN && oc < COUTR) ? w[(oc * CIN + c) * 9 + s] : 0.0f;
    __nv_bfloat16 h = __float2bfloat16(v);
    wh[i] = h;
    wl[i] = __float2bfloat16(v - __bfloat162float(h));
}

// ---------------- correlation (cp.async double-buffered, unchanged) ----------
__global__ void __launch_bounds__(256, 2) k_corr(const float* __restrict__ x1,
                                                 const float* __restrict__ x2) {
    __shared__ __align__(16) float x2s[2][4][16][40];
    const int tid = threadIdx.x;
    const int col = tid & 31, row = tid >> 5;
    const int w0 = blockIdx.x * 32, h0 = blockIdx.y * 8, b = blockIdx.z;

    float acc[81];
#pragma unroll
    for (int s = 0; s < 81; s++) acc[s] = 0.f;

    auto load_chunk = [&](int c0, int buf) {
        float* base = &x2s[buf][0][0][0];
        for (int idx = tid; idx < 4 * 16 * 40; idx += 256) {
            int c = idx / 640, r2 = idx % 640, rr = r2 / 40, cc = r2 % 40;
            int gh = h0 + rr - 4, gw = w0 + cc - 4;
            bool ok = (gh >= 0 && gh < H_ && gw >= 0 && gw < W_);
            const float* src = x2 + ((size_t)(b * C_ + c0 + c) * H_ + (ok ? gh : 0)) * W_ + (ok ? gw : 0);
            cpa4(base + idx, src, ok);
        }
    };

    load_chunk(0, 0);
    cpa_commit();

    int p = 0;
    for (int c0 = 0; c0 < C_; c0 += 4, p ^= 1) {
        cpa_wait_all();
        __syncthreads();
        if (c0 + 4 < C_) load_chunk(c0 + 4, p ^ 1);
        cpa_commit();

        float x1r[4];
#pragma unroll
        for (int c = 0; c < 4; c++)
            x1r[c] = x1[((b * C_ + c0 + c) * H_ + h0 + row) * W_ + w0 + col];
#pragma unroll
        for (int c = 0; c < 4; c++) {
            float v = x1r[c];
#pragma unroll
            for (int dy = 0; dy < 9; dy++)
#pragma unroll
                for (int dx = 0; dx < 9; dx++)
                    acc[dy * 9 + dx] += v * x2s[p][c][row + dy][col + dx];
        }
    }
#pragma unroll
    for (int s = 0; s < 81; s++)
        g_corr[((b * S_ + s) * H_ + h0 + row) * W_ + w0 + col] = acc[s] * (1.0f / 128.0f);
}

// ------- shift-decomposed mma.sync conv: 3x3 = 9 shifted 1x1 GEMMs, K = channels ----
// CTA: M=128 px (8 rows x 16 cols), N=COUT (padded). Halo tile 10x18 px x 64ch
// (hi/lo bf16, SW128) staged once per channel chunk; ldmatrix reads A directly.
// B [s][oc][c] triple-buffered (wait_group 1) via cp.async.
// D = Ah*Bh + Ah*Bl + Al*Bh (f32 acc).
template<int CIN, int Cpad, int NCHUNK, int COUT, bool SPLIT, bool LEAKY, int NWRITE, int LASTKC>
__global__ void __launch_bounds__(256, 2) k_convmma(const float* __restrict__ in,
                                                    const float* __restrict__ in2,
                                                    const __nv_bfloat16* __restrict__ wh,
                                                    const __nv_bfloat16* __restrict__ wl,
                                                    const float* __restrict__ bias,
                                                    float* __restrict__ out) {
    constexpr int ASZ = 180 * 128;       // halo: 180 px rows x 128B (64ch bf16)
    constexpr int BSZ = COUT * 128;      // B tile: COUT rows x 128B
    constexpr int NT = COUT / 8;
    constexpr int NTP = NT / 2;
    constexpr int T = NCHUNK * 9;

    extern __shared__ __align__(16) char smem_raw[];
    const uint32_t sb = smem_u32(smem_raw);
    const uint32_t Ah = sb, Al = sb + ASZ, Bb = sb + 2 * ASZ;
    const int tid = threadIdx.x, lane = tid & 31, wrp = tid >> 5;
    const int w0 = blockIdx.x * 16, h0 = blockIdx.y * 8, b = blockIdx.z;

    float acc[NT][4];
#pragma unroll
    for (int nt = 0; nt < NT; nt++)
#pragma unroll
        for (int j = 0; j < 4; j++) acc[nt][j] = 0.f;

    // ldmatrix per-lane components
    const int sub = lane >> 3, r8 = lane & 7;
    const int am = 16 * wrp + r8 + ((sub & 1) << 3);      // A matrix row (pixel in tile)
    const int pr = am >> 4, pc = am & 15;
    const int ak8 = (sub >> 1) << 3;
    const int bn_l = r8 + ((sub >> 1) << 3);
    const int bk8 = (sub & 1) << 3;

    // ---- halo stage: fixed-trip unrolled so ptxas batches the LDGs (MLP) ----
    auto stage_halo = [&](int i) {
        constexpr int HITER = (32 * 180 + 255) / 256;   // 23
#pragma unroll
        for (int j = 0; j < HITER; j++) {
            int e = tid + j * 256;
            if (e < 32 * 180) {
                int c2 = e / 180, hp = e - c2 * 180;
                int hr = hp / 18, hc = hp - hr * 18;
                int gh = h0 + hr - 1, gw = w0 + hc - 1;
                bool okp = (gh >= 0 && gh < H_ && gw >= 0 && gw < W_);
                int c0 = i * 64 + c2 * 2;
                float v0 = 0.f, v1 = 0.f;
                if (okp) {
                    if (SPLIT) {
                        if (c0 < 128) {
                            v0 = in[((size_t)(b * 128 + c0    ) * H_ + gh) * W_ + gw];
                            v1 = in[((size_t)(b * 128 + c0 + 1) * H_ + gh) * W_ + gw];
                        } else {
                            if (c0     < 209) v0 = in2[((size_t)(b * 81 + (c0     - 128)) * H_ + gh) * W_ + gw];
                            if (c0 + 1 < 209) v1 = in2[((size_t)(b * 81 + (c0 + 1 - 128)) * H_ + gh) * W_ + gw];
                        }
                    } else {
                        if (c0     < CIN) v0 = in[((size_t)(b * CIN + c0    ) * H_ + gh) * W_ + gw];
                        if (c0 + 1 < CIN) v1 = in[((size_t)(b * CIN + c0 + 1) * H_ + gh) * W_ + gw];
                    }
                }
                uint32_t hpk = bf16x2(v1, v0);
                float l0 = v0 - __uint_as_float(hpk << 16);
                float l1 = v1 - __uint_as_float(hpk & 0xffff0000u);
                uint32_t lpk = bf16x2(l1, l0);
                uint32_t off = (uint32_t)hp * 128 + (((uint32_t)c2 * 4) ^ ((uint32_t)(hp & 7) << 4));
                *(uint32_t*)(smem_raw + off)       = hpk;
                *(uint32_t*)(smem_raw + ASZ + off) = lpk;
            }
        }
    };
    // ---- B prefetch for global shift-iteration t1 into buffer `buf` (0..2) ----
    auto stage_B = [&](int t1, int buf) {
        int s = t1 % 9, i = t1 / 9;
#pragma unroll
        for (int j = 0; j < (COUT * 16 + 255) / 256; j++) {
            int q = tid + j * 256;
            if (q < COUT * 16) {
                int split = q / (COUT * 8);
                int r = q - split * (COUT * 8);
                int oc = r >> 3, seg = r & 7;
                const __nv_bfloat16* src =
                    (split ? wl : wh) + (size_t)(s * COUT + oc) * Cpad + i * 64 + seg * 8;
                cpa16(Bb + (uint32_t)(buf * 2 + split) * BSZ + sw128((uint32_t)(oc * 128 + seg * 16)), src);
            }
        }
        cpa_commit();
    };

    stage_B(0, 0);
    if (T > 1) stage_B(1, 1);
    int t = 0;
    for (int i = 0; i < NCHUNK; i++) {
        __syncthreads();                 // all warps done reading previous halo
        stage_halo(i);
        const int kcmax = (i == NCHUNK - 1) ? LASTKC : 4;
#pragma unroll 1
        for (int s = 0; s < 9; s++) {
            if (t + 1 < T) cpa_wait1(); else cpa_wait_all();   // B(t) landed
            __syncthreads();             // halo + B visible; warps aligned
            if (t + 2 < T) stage_B(t + 2, (t + 2) % 3);
            const int buf = t % 3;

            const int ky = s / 3, kx = s - ky * 3;
            const int hr = (pr + ky) * 18 + (pc + kx);
            const uint32_t arow = (uint32_t)hr * 128;
            const uint32_t axor = (uint32_t)(hr & 7) << 4;
            const uint32_t Bhc = Bb + (uint32_t)(buf * 2 + 0) * BSZ;
            const uint32_t Blc = Bb + (uint32_t)(buf * 2 + 1) * BSZ;
#pragma unroll
            for (int kc = 0; kc < 4; kc++) {
                if (kc < kcmax) {
                    uint32_t ka = ((uint32_t)((kc * 16 + ak8) * 2)) ^ axor;
                    uint32_t ahf[4], alf[4];
                    ldsm4(ahf, Ah + arow + ka);
                    ldsm4(alf, Al + arow + ka);
                    uint32_t bhf[NTP][4], blf[NTP][4];
#pragma unroll
                    for (int tp = 0; tp < NTP; tp++) {
                        int bn = tp * 16 + bn_l;
                        uint32_t boff = (uint32_t)bn * 128
                                      + (((uint32_t)((kc * 16 + bk8) * 2)) ^ ((uint32_t)(bn & 7) << 4));
                        ldsm4(bhf[tp], Bhc + boff);
                        ldsm4(blf[tp], Blc + boff);
                    }
#pragma unroll
                    for (int tp = 0; tp < NTP; tp++) {
                        mma_bf16(acc[2 * tp],     ahf, bhf[tp]);
                        mma_bf16(acc[2 * tp + 1], ahf, bhf[tp] + 2);
                    }
#pragma unroll
                    for (int tp = 0; tp < NTP; tp++) {
                        mma_bf16(acc[2 * tp],     ahf, blf[tp]);
                        mma_bf16(acc[2 * tp + 1], ahf, blf[tp] + 2);
                    }
#pragma unroll
                    for (int tp = 0; tp < NTP; tp++) {
                        mma_bf16(acc[2 * tp],     alf, bhf[tp]);
                        mma_bf16(acc[2 * tp + 1], alf, bhf[tp] + 2);
                    }
                }
            }
            t++;
        }
    }

    // ---- epilogue: registers -> gmem NCHW, bias + (optional) leaky ----
    const int m1 = 16 * wrp + lane / 4, m2 = m1 + 8;
    const int cb = (lane % 4) * 2;
    const int gh1 = h0 + (m1 >> 4), gw1 = w0 + (m1 & 15);
    const int gh2 = h0 + (m2 >> 4), gw2 = w0 + (m2 & 15);
#pragma unroll
    for (int nt = 0; nt < NT; nt++) {
        int n0 = nt * 8 + cb;
        if (n0 < NWRITE) {
            float b0v = bias[n0], b1v = bias[n0 + 1];
            float v00 = acc[nt][0] + b0v, v01 = acc[nt][1] + b1v;
            float v10 = acc[nt][2] + b0v, v11 = acc[nt][3] + b1v;
            if (LEAKY) {
                v00 = fmaxf(v00, 0.1f * v00); v01 = fmaxf(v01, 0.1f * v01);
                v10 = fmaxf(v10, 0.1f * v10); v11 = fmaxf(v11, 0.1f * v11);
            }
            out[((size_t)(b * NWRITE + n0    ) * H_ + gh1) * W_ + gw1] = v00;
            out[((size_t)(b * NWRITE + n0 + 1) * H_ + gh1) * W_ + gw1] = v01;
            out[((size_t)(b * NWRITE + n0    ) * H_ + gh2) * W_ + gw2] = v10;
            out[((size_t)(b * NWRITE + n0 + 1) * H_ + gh2) * W_ + gw2] = v11;
        }
    }
}

// ---------------- launch ----------------
extern "C" void kernel_launch(void* const* d_in, const int* in_sizes, int n_in,
                              void* d_out, int out_size) {
    (void)in_sizes; (void)n_in; (void)out_size;
    const float* x1 = (const float*)d_in[0];
    const float* x2 = (const float*)d_in[1];
    const float* w1 = (const float*)d_in[2];
    const float* b1 = (const float*)d_in[3];
    const float* w2 = (const float*)d_in[4];
    const float* b2 = (const float*)d_in[5];
    const float* w3 = (const float*)d_in[6];
    const float* b3 = (const float*)d_in[7];
    const float* w4 = (const float*)d_in[8];
    const float* b4 = (const float*)d_in[9];
    float* out = (float*)d_out;

    float *corr, *h1, *h2, *h3;
    __nv_bfloat16 *w1h, *w1l, *w2h, *w2l, *w3h, *w3l, *w4h, *w4l;
    cudaGetSymbolAddress((void**)&corr, g_corr);
    cudaGetSymbolAddress((void**)&h1,   g_h1);
    cudaGetSymbolAddress((void**)&h2,   g_h2);
    cudaGetSymbolAddress((void**)&h3,   g_h3);
    cudaGetSymbolAddress((void**)&w1h,  g_w1h);
    cudaGetSymbolAddress((void**)&w1l,  g_w1l);
    cudaGetSymbolAddress((void**)&w2h,  g_w2h);
    cudaGetSymbolAddress((void**)&w2l,  g_w2l);
    cudaGetSymbolAddress((void**)&w3h,  g_w3h);
    cudaGetSymbolAddress((void**)&w3l,  g_w3l);
    cudaGetSymbolAddress((void**)&w4h,  g_w4h);
    cudaGetSymbolAddress((void**)&w4l,  g_w4l);

    // smem: hi/lo halo (2 x 23040) + B triple buffer (3 x 2 x BSZ)
    constexpr int SM64 = 2 * 180 * 128 + 6 * 64 * 128;   // 95232
    constexpr int SM32 = 2 * 180 * 128 + 6 * 32 * 128;   // 70656
    constexpr int SM16 = 2 * 180 * 128 + 6 * 16 * 128;   // 58368
    static bool attr_done = false;
    if (!attr_done) {
        cudaFuncSetAttribute(k_convmma<209, 256, 4, 64, true , true , 64, 2>, cudaFuncAttributeMaxDynamicSharedMemorySize, SM64);
        cudaFuncSetAttribute(k_convmma< 64,  64, 1, 64, false, true , 64, 4>, cudaFuncAttributeMaxDynamicSharedMemorySize, SM64);
        cudaFuncSetAttribute(k_convmma< 64,  64, 1, 32, false, true , 32, 4>, cudaFuncAttributeMaxDynamicSharedMemorySize, SM32);
        cudaFuncSetAttribute(k_convmma< 32,  64, 1, 16, false, false,  2, 2>, cudaFuncAttributeMaxDynamicSharedMemorySize, SM16);
        attr_done = true;
    }

    k_reorder_split<<<(9 * 64 * 256 + 255) / 256, 256>>>(w1, w1h, w1l, 209, 64, 256, 64);
    k_reorder_split<<<(9 * 64 * 64  + 255) / 256, 256>>>(w2, w2h, w2l,  64, 64,  64, 64);
    k_reorder_split<<<(9 * 32 * 64  + 255) / 256, 256>>>(w3, w3h, w3l,  64, 32,  64, 32);
    k_reorder_split<<<(9 * 16 * 64  + 255) / 256, 256>>>(w4, w4h, w4l,  32, 16,  64,  2);

    dim3 gridC(W_ / 32, H_ / 8, B_);   // (7, 16, 8)  corr
    dim3 gridT(W_ / 16, H_ / 8, B_);   // (14, 16, 8) mma convs

    k_corr<<<gridC, 256>>>(x1, x2);
    k_convmma<209, 256, 4, 64, true , true , 64, 2><<<gridT, 256, SM64>>>(x1, corr, w1h, w1l, b1, h1);
    k_convmma< 64,  64, 1, 64, false, true , 64, 4><<<gridT, 256, SM64>>>(h1, nullptr, w2h, w2l, b2, h2);
    k_convmma< 64,  64, 1, 32, false, true , 32, 4><<<gridT, 256, SM32>>>(h2, nullptr, w3h, w3l, b3, h3);
    k_convmma< 32,  64, 1, 16, false, false,  2, 2><<<gridT, 256, SM16>>>(h3, nullptr, w4h, w4l, b4, out);
}